// round 2
// baseline (speedup 1.0000x reference)
#include <cuda_runtime.h>
#include <math.h>

// Problem constants
constexpr int T_ = 64;
constexpr int B_ = 256;
constexpr int NITEMS = 100000;
constexpr int E_ = 128;
constexpr int H_ = 512;
constexpr int NH_ = 8;
constexpr int G4_ = 4 * H_;   // 2048
constexpr int TB_ = T_ * B_;  // 16384

// ---------------- scratch (device globals) ----------------------------------
__device__ float g_embs[TB_ * E_];
__device__ float g_bsum[G4_];
__device__ float g_Xg[TB_ * G4_];
__device__ float g_hbuf[2][B_ * H_];
__device__ float g_c[B_ * H_];
__device__ float g_lstm_out[TB_ * H_];     // (B,T,H)
__device__ float g_Q[TB_ * H_];
__device__ float g_K[TB_ * H_];
__device__ float g_V[TB_ * H_];
__device__ float g_wout[TB_ * H_];
__device__ float g_mho[TB_ * H_];
__device__ float g_pooled[B_ * H_];
__device__ float g_ae[B_ * E_];

// ---------------- small kernels ---------------------------------------------
__global__ void zero_init_kernel() {
    int i = blockIdx.x * blockDim.x + threadIdx.x;
    if (i < B_ * H_) { g_hbuf[0][i] = 0.f; g_c[i] = 0.f; }
}

__global__ void bias_sum_kernel(const float* __restrict__ b_ih,
                                const float* __restrict__ b_hh) {
    int i = blockIdx.x * blockDim.x + threadIdx.x;
    if (i < G4_) g_bsum[i] = b_ih[i] + b_hh[i];
}

__global__ void gather_square_kernel(const int* __restrict__ x,
                                     const float* __restrict__ emb) {
    int fi = blockIdx.x * blockDim.x + threadIdx.x;
    int row = fi >> 5;
    int c4  = fi & 31;
    int id = x[row];
    float4 v = ((const float4*)(emb + (size_t)id * E_))[c4];
    float4 o;
    o.x = v.x * v.x; o.y = v.y * v.y; o.z = v.z * v.z; o.w = v.w * v.w;
    ((float4*)g_embs)[fi] = o;
}

// ---------------- SGEMM v2: C = A(MxK) * W(NxK)^T + bias --------------------
// 128x128 tile, Kc=16, register-prefetch double-buffered shared memory.
template<bool CHECKN>
__global__ __launch_bounds__(256, 2)
void sgemm_v2(const float* __restrict__ A, const float* __restrict__ W,
              const float* __restrict__ bias, float* __restrict__ C,
              int M, int N, int K) {
    __shared__ __align__(16) float As[2][16][128];
    __shared__ __align__(16) float Bs[2][16][128];

    const int tid = threadIdx.x;
    const int bm = blockIdx.y * 128;
    const int bn = blockIdx.x * 128;
    const int lr = tid >> 1;            // 0..127
    const int lk = (tid & 1) << 3;      // 0 or 8

    bool wok = true;
    int wrow = bn + lr;
    if (CHECKN) { wok = (wrow < N); if (!wok) wrow = N - 1; }
    const float* Ap = A + (size_t)(bm + lr) * K + lk;
    const float* Wp = W + (size_t)wrow * K + lk;

    const int tx = tid & 15;
    const int ty = tid >> 4;

    float acc[8][8];
#pragma unroll
    for (int i = 0; i < 8; i++)
#pragma unroll
        for (int j = 0; j < 8; j++) acc[i][j] = 0.f;

    float4 pa0, pa1, pb0, pb1;
    // prologue: chunk 0
    pa0 = *(const float4*)(Ap);
    pa1 = *(const float4*)(Ap + 4);
    if (!CHECKN || wok) {
        pb0 = *(const float4*)(Wp);
        pb1 = *(const float4*)(Wp + 4);
    } else {
        pb0 = make_float4(0.f, 0.f, 0.f, 0.f);
        pb1 = pb0;
    }
    {
        As[0][lk + 0][lr] = pa0.x; As[0][lk + 1][lr] = pa0.y;
        As[0][lk + 2][lr] = pa0.z; As[0][lk + 3][lr] = pa0.w;
        As[0][lk + 4][lr] = pa1.x; As[0][lk + 5][lr] = pa1.y;
        As[0][lk + 6][lr] = pa1.z; As[0][lk + 7][lr] = pa1.w;
        Bs[0][lk + 0][lr] = pb0.x; Bs[0][lk + 1][lr] = pb0.y;
        Bs[0][lk + 2][lr] = pb0.z; Bs[0][lk + 3][lr] = pb0.w;
        Bs[0][lk + 4][lr] = pb1.x; Bs[0][lk + 5][lr] = pb1.y;
        Bs[0][lk + 6][lr] = pb1.z; Bs[0][lk + 7][lr] = pb1.w;
    }
    __syncthreads();

    int buf = 0;
    for (int k0 = 16; k0 < K; k0 += 16) {
        // prefetch next chunk to registers
        pa0 = *(const float4*)(Ap + k0);
        pa1 = *(const float4*)(Ap + k0 + 4);
        if (!CHECKN || wok) {
            pb0 = *(const float4*)(Wp + k0);
            pb1 = *(const float4*)(Wp + k0 + 4);
        } else {
            pb0 = make_float4(0.f, 0.f, 0.f, 0.f);
            pb1 = pb0;
        }
        // compute on current buffer
#pragma unroll
        for (int kk = 0; kk < 16; kk++) {
            float4 a0 = *(const float4*)&As[buf][kk][ty * 8];
            float4 a1 = *(const float4*)&As[buf][kk][ty * 8 + 4];
            float4 b0 = *(const float4*)&Bs[buf][kk][tx * 8];
            float4 b1 = *(const float4*)&Bs[buf][kk][tx * 8 + 4];
            float a[8] = {a0.x, a0.y, a0.z, a0.w, a1.x, a1.y, a1.z, a1.w};
            float b[8] = {b0.x, b0.y, b0.z, b0.w, b1.x, b1.y, b1.z, b1.w};
#pragma unroll
            for (int i = 0; i < 8; i++)
#pragma unroll
                for (int j = 0; j < 8; j++) acc[i][j] += a[i] * b[j];
        }
        // store prefetched chunk to the other buffer
        int nb = buf ^ 1;
        As[nb][lk + 0][lr] = pa0.x; As[nb][lk + 1][lr] = pa0.y;
        As[nb][lk + 2][lr] = pa0.z; As[nb][lk + 3][lr] = pa0.w;
        As[nb][lk + 4][lr] = pa1.x; As[nb][lk + 5][lr] = pa1.y;
        As[nb][lk + 6][lr] = pa1.z; As[nb][lk + 7][lr] = pa1.w;
        Bs[nb][lk + 0][lr] = pb0.x; Bs[nb][lk + 1][lr] = pb0.y;
        Bs[nb][lk + 2][lr] = pb0.z; Bs[nb][lk + 3][lr] = pb0.w;
        Bs[nb][lk + 4][lr] = pb1.x; Bs[nb][lk + 5][lr] = pb1.y;
        Bs[nb][lk + 6][lr] = pb1.z; Bs[nb][lk + 7][lr] = pb1.w;
        __syncthreads();
        buf = nb;
    }
    // last chunk
#pragma unroll
    for (int kk = 0; kk < 16; kk++) {
        float4 a0 = *(const float4*)&As[buf][kk][ty * 8];
        float4 a1 = *(const float4*)&As[buf][kk][ty * 8 + 4];
        float4 b0 = *(const float4*)&Bs[buf][kk][tx * 8];
        float4 b1 = *(const float4*)&Bs[buf][kk][tx * 8 + 4];
        float a[8] = {a0.x, a0.y, a0.z, a0.w, a1.x, a1.y, a1.z, a1.w};
        float b[8] = {b0.x, b0.y, b0.z, b0.w, b1.x, b1.y, b1.z, b1.w};
#pragma unroll
        for (int i = 0; i < 8; i++)
#pragma unroll
            for (int j = 0; j < 8; j++) acc[i][j] += a[i] * b[j];
    }

#pragma unroll
    for (int i = 0; i < 8; i++) {
        int m = bm + ty * 8 + i;
#pragma unroll
        for (int j = 0; j < 8; j++) {
            int n = bn + tx * 8 + j;
            if (!CHECKN || n < N) {
                float v = acc[i][j];
                if (bias) v += bias[n];
                C[(size_t)m * N + n] = v;
            }
        }
    }
}

// ---------------- fused LSTM recurrent step v2 ------------------------------
// grid (16 jj-blocks, 8 b-blocks) = 128 blocks, 128 threads.
// Block tile: 32 b x 32 jh (x 4 gates = 128 W rows). Thread: 4b x (2jh x 4g).
__device__ __forceinline__ float sigmoidf_(float x) {
    return 1.f / (1.f + expf(-x));
}

__global__ __launch_bounds__(128)
void lstm_step_v2(const float* __restrict__ Xg_t,   // (B, 4H)
                  const float* __restrict__ w_hh,   // (4H, H)
                  const float* __restrict__ h_in,   // (B, H)
                  float* __restrict__ h_out,        // (B, H)
                  const int* __restrict__ lengths,
                  int t) {
    __shared__ __align__(16) float hs[2][16][36];    // [k][b]
    __shared__ __align__(16) float ws[2][16][132];   // [k][l], l = jj*4+g

    const int tid = threadIdx.x;
    const int tx = tid & 15;     // jj-group (2 jh each)
    const int ty = tid >> 4;     // b-group (4 b each)
    const int jj0 = blockIdx.x * 32;   // hidden-index base of this block
    const int b0 = blockIdx.y * 32;

    // global load indices
    const int hb = tid >> 2;               // 0..31 (b for h loads)
    const int hq = (tid & 3) << 2;         // k-offset 0,4,8,12
    const float* hp = h_in + (size_t)(b0 + hb) * H_ + hq;

    // W loads: 4 float4 per thread per chunk
    const float* wp[4];
    int wl[4];
#pragma unroll
    for (int p = 0; p < 4; p++) {
        int idx = tid + (p << 7);          // 0..511
        int l = idx >> 2;                  // 0..127
        int q = (idx & 3) << 2;
        int g = l & 3;
        int jj = l >> 2;
        wl[p] = l;
        wp[p] = w_hh + (size_t)(g * H_ + jj0 + jj) * H_ + q;
    }

    float acc[4][8];
#pragma unroll
    for (int i = 0; i < 4; i++)
#pragma unroll
        for (int j = 0; j < 8; j++) acc[i][j] = 0.f;

    float4 ph, pw[4];
    // prologue chunk 0
    ph = *(const float4*)(hp);
#pragma unroll
    for (int p = 0; p < 4; p++) pw[p] = *(const float4*)(wp[p]);
    hs[0][hq + 0][hb] = ph.x; hs[0][hq + 1][hb] = ph.y;
    hs[0][hq + 2][hb] = ph.z; hs[0][hq + 3][hb] = ph.w;
#pragma unroll
    for (int p = 0; p < 4; p++) {
        int q = ((tid + (p << 7)) & 3) << 2;
        ws[0][q + 0][wl[p]] = pw[p].x; ws[0][q + 1][wl[p]] = pw[p].y;
        ws[0][q + 2][wl[p]] = pw[p].z; ws[0][q + 3][wl[p]] = pw[p].w;
    }
    __syncthreads();

    int buf = 0;
    for (int k0 = 16; k0 < H_; k0 += 16) {
        ph = *(const float4*)(hp + k0);
#pragma unroll
        for (int p = 0; p < 4; p++) pw[p] = *(const float4*)(wp[p] + k0);
#pragma unroll
        for (int kk = 0; kk < 16; kk++) {
            float4 hv = *(const float4*)&hs[buf][kk][ty * 4];
            float4 w0 = *(const float4*)&ws[buf][kk][tx * 8];
            float4 w1 = *(const float4*)&ws[buf][kk][tx * 8 + 4];
            float h[4] = {hv.x, hv.y, hv.z, hv.w};
            float w[8] = {w0.x, w0.y, w0.z, w0.w, w1.x, w1.y, w1.z, w1.w};
#pragma unroll
            for (int i = 0; i < 4; i++)
#pragma unroll
                for (int j = 0; j < 8; j++) acc[i][j] += h[i] * w[j];
        }
        int nb = buf ^ 1;
        hs[nb][hq + 0][hb] = ph.x; hs[nb][hq + 1][hb] = ph.y;
        hs[nb][hq + 2][hb] = ph.z; hs[nb][hq + 3][hb] = ph.w;
#pragma unroll
        for (int p = 0; p < 4; p++) {
            int q = ((tid + (p << 7)) & 3) << 2;
            ws[nb][q + 0][wl[p]] = pw[p].x; ws[nb][q + 1][wl[p]] = pw[p].y;
            ws[nb][q + 2][wl[p]] = pw[p].z; ws[nb][q + 3][wl[p]] = pw[p].w;
        }
        __syncthreads();
        buf = nb;
    }
#pragma unroll
    for (int kk = 0; kk < 16; kk++) {
        float4 hv = *(const float4*)&hs[buf][kk][ty * 4];
        float4 w0 = *(const float4*)&ws[buf][kk][tx * 8];
        float4 w1 = *(const float4*)&ws[buf][kk][tx * 8 + 4];
        float h[4] = {hv.x, hv.y, hv.z, hv.w};
        float w[8] = {w0.x, w0.y, w0.z, w0.w, w1.x, w1.y, w1.z, w1.w};
#pragma unroll
        for (int i = 0; i < 4; i++)
#pragma unroll
            for (int j = 0; j < 8; j++) acc[i][j] += h[i] * w[j];
    }

    // epilogue: gates
#pragma unroll
    for (int i = 0; i < 4; i++) {
        int b = b0 + ty * 4 + i;
        int len = lengths[b];
        const float* xg = Xg_t + (size_t)b * G4_;
#pragma unroll
        for (int u = 0; u < 2; u++) {
            int jh = jj0 + tx * 2 + u;
            float gi = sigmoidf_(acc[i][u * 4 + 0] + xg[jh]);
            float gf = sigmoidf_(acc[i][u * 4 + 1] + xg[H_ + jh]);
            float gg = tanhf(acc[i][u * 4 + 2] + xg[2 * H_ + jh]);
            float go = sigmoidf_(acc[i][u * 4 + 3] + xg[3 * H_ + jh]);
            float cn = gf * g_c[b * H_ + jh] + gi * gg;
            g_c[b * H_ + jh] = cn;
            float hn = go * tanhf(cn);
            h_out[b * H_ + jh] = hn;
            g_lstm_out[(size_t)(b * T_ + t) * H_ + jh] = (t < len) ? hn : 0.f;
        }
    }
}

// ---------------- attention: one block per (b, head) ------------------------
__global__ __launch_bounds__(256)
void attention_kernel(const float* __restrict__ Q,
                      const float* __restrict__ Kmat,
                      const float* __restrict__ V,
                      const int* __restrict__ lengths,
                      float* __restrict__ Wout) {
    __shared__ float qs[64 * 64];
    __shared__ float ks[64 * 64];
    __shared__ float ss[64 * 64];
    const int b = blockIdx.x, nh = blockIdx.y;
    const int tid = threadIdx.x;
    const int len = lengths[b];
    const size_t base = ((size_t)b * 64) * 512 + nh * 64;

#pragma unroll
    for (int l = 0; l < 4; l++) {
        int fidx = tid + (l << 8);
        int r = fidx & 63, c4 = fidx >> 6;
        float4 qv = *(const float4*)(Q + base + (size_t)r * 512 + c4 * 4);
        float4 kv = *(const float4*)(Kmat + base + (size_t)r * 512 + c4 * 4);
        qs[(c4 * 4 + 0) * 64 + r] = qv.x; qs[(c4 * 4 + 1) * 64 + r] = qv.y;
        qs[(c4 * 4 + 2) * 64 + r] = qv.z; qs[(c4 * 4 + 3) * 64 + r] = qv.w;
        ks[(c4 * 4 + 0) * 64 + r] = kv.x; ks[(c4 * 4 + 1) * 64 + r] = kv.y;
        ks[(c4 * 4 + 2) * 64 + r] = kv.z; ks[(c4 * 4 + 3) * 64 + r] = kv.w;
    }
    __syncthreads();

    const int tx = tid & 15, ty = tid >> 4;
    const int r0 = ty * 4, c0 = tx * 4;
    float acc[4][4];
#pragma unroll
    for (int i = 0; i < 4; i++)
#pragma unroll
        for (int j = 0; j < 4; j++) acc[i][j] = 0.f;

#pragma unroll 8
    for (int k = 0; k < 64; k++) {
        float4 aq = *(const float4*)&qs[k * 64 + r0];
        float4 bk = *(const float4*)&ks[k * 64 + c0];
        float a[4] = {aq.x, aq.y, aq.z, aq.w};
        float bb[4] = {bk.x, bk.y, bk.z, bk.w};
#pragma unroll
        for (int i = 0; i < 4; i++)
#pragma unroll
            for (int j = 0; j < 4; j++) acc[i][j] += a[i] * bb[j];
    }
#pragma unroll
    for (int i = 0; i < 4; i++)
#pragma unroll
        for (int j = 0; j < 4; j++) {
            int c = c0 + j;
            ss[(r0 + i) * 64 + c] = (c < len) ? acc[i][j] * 0.125f : -1e30f;
        }
    __syncthreads();

    float* vs = qs;
#pragma unroll
    for (int l = 0; l < 4; l++) {
        int fidx = tid + (l << 8);
        int r = fidx >> 4, c4 = fidx & 15;
        ((float4*)vs)[fidx] = *(const float4*)(V + base + (size_t)r * 512 + c4 * 4);
    }
    if (tid < 64) {
        float m = -1e30f;
#pragma unroll 8
        for (int c = 0; c < 64; c++) m = fmaxf(m, ss[tid * 64 + c]);
        float s = 0.f;
#pragma unroll 8
        for (int c = 0; c < 64; c++) {
            float e = expf(ss[tid * 64 + c] - m);
            ss[tid * 64 + c] = e;
            s += e;
        }
        float inv = 1.f / s;
#pragma unroll 8
        for (int c = 0; c < 64; c++) ss[tid * 64 + c] *= inv;
    }
    __syncthreads();

    float o[4][4];
#pragma unroll
    for (int i = 0; i < 4; i++)
#pragma unroll
        for (int j = 0; j < 4; j++) o[i][j] = 0.f;
#pragma unroll 8
    for (int k = 0; k < 64; k++) {
        float a[4];
#pragma unroll
        for (int i = 0; i < 4; i++) a[i] = ss[(r0 + i) * 64 + k];
        float4 vv4 = *(const float4*)&vs[k * 64 + c0];
        float vv[4] = {vv4.x, vv4.y, vv4.z, vv4.w};
#pragma unroll
        for (int i = 0; i < 4; i++)
#pragma unroll
            for (int j = 0; j < 4; j++) o[i][j] += a[i] * vv[j];
    }
#pragma unroll
    for (int i = 0; i < 4; i++) {
        float4 ov = make_float4(o[i][0], o[i][1], o[i][2], o[i][3]);
        *(float4*)(Wout + base + (size_t)(r0 + i) * 512 + c0) = ov;
    }
}

// ---------------- pooling + hidden_to_embedding -----------------------------
__global__ void meanpool_kernel() {
    int idx = blockIdx.x * blockDim.x + threadIdx.x;
    int b = idx >> 9, j = idx & 511;
    float s = 0.f;
#pragma unroll 16
    for (int t = 0; t < 64; t++) s += g_mho[(size_t)(b * 64 + t) * 512 + j];
    g_pooled[idx] = s * (1.f / 64.f);
}

__global__ void h2e_kernel(const float* __restrict__ w_h2e,
                           const float* __restrict__ b_h2e) {
    __shared__ float sp[H_];
    int b = blockIdx.x, e = threadIdx.x;
    for (int k = e; k < H_; k += 128) sp[k] = g_pooled[b * H_ + k];
    __syncthreads();
    float acc = b_h2e[e];
    const float* wr = w_h2e + (size_t)e * H_;
#pragma unroll 8
    for (int k = 0; k < H_; k++) acc += sp[k] * wr[k];
    g_ae[b * E_ + e] = acc;
}

// ---------------- entry point -----------------------------------------------
extern "C" void kernel_launch(void* const* d_in, const int* in_sizes, int n_in,
                              void* d_out, int out_size) {
    const int*   x       = (const int*)d_in[0];
    const int*   lengths = (const int*)d_in[1];
    const float* emb     = (const float*)d_in[2];
    const float* w_ih    = (const float*)d_in[3];
    const float* w_hh    = (const float*)d_in[4];
    const float* b_ih    = (const float*)d_in[5];
    const float* b_hh    = (const float*)d_in[6];
    const float* wq      = (const float*)d_in[7];
    const float* bq      = (const float*)d_in[8];
    const float* wk      = (const float*)d_in[9];
    const float* bk      = (const float*)d_in[10];
    const float* wv      = (const float*)d_in[11];
    const float* bv      = (const float*)d_in[12];
    const float* wo      = (const float*)d_in[13];
    const float* bo      = (const float*)d_in[14];
    const float* w_h2e   = (const float*)d_in[15];
    const float* b_h2e   = (const float*)d_in[16];
    float* out = (float*)d_out;

    float *p_embs, *p_bsum, *p_Xg, *p_h, *p_lo, *p_Q, *p_K, *p_V, *p_w, *p_mho, *p_ae;
    cudaGetSymbolAddress((void**)&p_embs, g_embs);
    cudaGetSymbolAddress((void**)&p_bsum, g_bsum);
    cudaGetSymbolAddress((void**)&p_Xg,   g_Xg);
    cudaGetSymbolAddress((void**)&p_h,    g_hbuf);
    cudaGetSymbolAddress((void**)&p_lo,   g_lstm_out);
    cudaGetSymbolAddress((void**)&p_Q,    g_Q);
    cudaGetSymbolAddress((void**)&p_K,    g_K);
    cudaGetSymbolAddress((void**)&p_V,    g_V);
    cudaGetSymbolAddress((void**)&p_w,    g_wout);
    cudaGetSymbolAddress((void**)&p_mho,  g_mho);
    cudaGetSymbolAddress((void**)&p_ae,   g_ae);
    float* p_h0 = p_h;
    float* p_h1 = p_h + B_ * H_;

    zero_init_kernel<<<(B_ * H_ + 255) / 256, 256>>>();
    bias_sum_kernel<<<(G4_ + 255) / 256, 256>>>(b_ih, b_hh);
    gather_square_kernel<<<(TB_ * E_ / 4 + 255) / 256, 256>>>(x, emb);

    // Xg = embs @ w_ih^T + (b_ih + b_hh)
    sgemm_v2<false><<<dim3(G4_ / 128, TB_ / 128), 256>>>(p_embs, w_ih, p_bsum, p_Xg, TB_, G4_, E_);

    // LSTM recurrence
    for (int t = 0; t < T_; t++) {
        const float* hin = (t & 1) ? p_h1 : p_h0;
        float* hout      = (t & 1) ? p_h0 : p_h1;
        lstm_step_v2<<<dim3(H_ / 32, B_ / 32), 128>>>(
            p_Xg + (size_t)t * B_ * G4_, w_hh, hin, hout, lengths, t);
    }

    // QKV projections
    sgemm_v2<false><<<dim3(H_ / 128, TB_ / 128), 256>>>(p_lo, wq, bq, p_Q, TB_, H_, H_);
    sgemm_v2<false><<<dim3(H_ / 128, TB_ / 128), 256>>>(p_lo, wk, bk, p_K, TB_, H_, H_);
    sgemm_v2<false><<<dim3(H_ / 128, TB_ / 128), 256>>>(p_lo, wv, bv, p_V, TB_, H_, H_);

    attention_kernel<<<dim3(B_, NH_), 256>>>(p_Q, p_K, p_V, lengths, p_w);

    // output projection
    sgemm_v2<false><<<dim3(H_ / 128, TB_ / 128), 256>>>(p_w, wo, bo, p_mho, TB_, H_, H_);

    meanpool_kernel<<<(B_ * H_ + 255) / 256, 256>>>();
    h2e_kernel<<<B_, 128>>>(w_h2e, b_h2e);

    // final scores = ae @ emb^T
    sgemm_v2<true><<<dim3((NITEMS + 127) / 128, B_ / 128), 256>>>(p_ae, emb, nullptr, out, B_, NITEMS, E_);
}

// round 5
// speedup vs baseline: 1.7454x; 1.7454x over previous
#include <cuda_runtime.h>
#include <math.h>
#include <stdint.h>

// Problem constants
constexpr int T_ = 64;
constexpr int B_ = 256;
constexpr int NITEMS = 100000;
constexpr int E_ = 128;
constexpr int H_ = 512;
constexpr int NH_ = 8;
constexpr int G4_ = 4 * H_;   // 2048
constexpr int TB_ = T_ * B_;  // 16384

// ---------------- scratch (device globals) ----------------------------------
__device__ float g_embs[TB_ * E_];
__device__ float g_bsum[G4_];
__device__ float g_Xg[TB_ * G4_];
__device__ float g_hbuf[2][B_ * H_];
__device__ float g_c[B_ * H_];
__device__ float g_lstm_out[TB_ * H_];     // (B,T,H)
__device__ float g_Q[TB_ * H_];
__device__ float g_K[TB_ * H_];
__device__ float g_V[TB_ * H_];
__device__ float g_wout[TB_ * H_];
__device__ float g_mho[TB_ * H_];
__device__ float g_ae[B_ * E_];

// ---------------- helpers ----------------------------------------------------
__device__ __forceinline__ float tf32r(float x) {
    uint32_t u;
    asm("cvt.rna.tf32.f32 %0, %1;" : "=r"(u) : "f"(x));
    return __uint_as_float(u);
}

__device__ __forceinline__ void mma_tf32(float c[4],
                                         float a0, float a1, float a2, float a3,
                                         float b0, float b1) {
    asm volatile(
        "mma.sync.aligned.m16n8k8.row.col.f32.tf32.tf32.f32 "
        "{%0,%1,%2,%3},{%4,%5,%6,%7},{%8,%9},{%0,%1,%2,%3};"
        : "+f"(c[0]), "+f"(c[1]), "+f"(c[2]), "+f"(c[3])
        : "r"(__float_as_uint(a0)), "r"(__float_as_uint(a1)),
          "r"(__float_as_uint(a2)), "r"(__float_as_uint(a3)),
          "r"(__float_as_uint(b0)), "r"(__float_as_uint(b1)));
}

__device__ __forceinline__ float sigmoidf_(float x) {
    return 1.f / (1.f + expf(-x));
}

// ---------------- small kernels ---------------------------------------------
__global__ void zero_init_kernel() {
    int i = blockIdx.x * blockDim.x + threadIdx.x;
    if (i < B_ * H_) { g_hbuf[0][i] = 0.f; g_c[i] = 0.f; }
}

__global__ void bias_sum_kernel(const float* __restrict__ b_ih,
                                const float* __restrict__ b_hh) {
    int i = blockIdx.x * blockDim.x + threadIdx.x;
    if (i < G4_) g_bsum[i] = b_ih[i] + b_hh[i];
}

__global__ void gather_square_kernel(const int* __restrict__ x,
                                     const float* __restrict__ emb) {
    int fi = blockIdx.x * blockDim.x + threadIdx.x;
    int row = fi >> 5;
    int c4  = fi & 31;
    int id = x[row];
    float4 v = ((const float4*)(emb + (size_t)id * E_))[c4];
    float4 o;
    o.x = v.x * v.x; o.y = v.y * v.y; o.z = v.z * v.z; o.w = v.w * v.w;
    ((float4*)g_embs)[fi] = o;
}

// ---------------- tf32 tensor-core GEMM: C = A(MxK) W(NxK)^T + bias ----------
// Block 128x128, Kc=16 double buffered (single sync per chunk).
// 8 warps: 4 (m, 32 rows) x 2 (n, 64 cols). smem stride 20 -> conflict-free.
template<bool CHECKN>
__global__ __launch_bounds__(256, 1)
void gemm_tf32(const float* __restrict__ A, const float* __restrict__ W,
               const float* __restrict__ bias, float* __restrict__ C,
               int M, int N, int K) {
    __shared__ __align__(16) float As[2][128][20];
    __shared__ __align__(16) float Bs[2][128][20];

    const int tid = threadIdx.x;
    const int lane = tid & 31;
    const int wid = tid >> 5;
    const int wm = (wid & 3) * 32;
    const int wn = (wid >> 2) * 64;
    const int bm = blockIdx.y * 128;
    const int bn = blockIdx.x * 128;
    const int lr = tid >> 1;            // 0..127
    const int lk = (tid & 1) * 8;       // 0 or 8

    int wrow = bn + lr;
    bool wok = true;
    if (CHECKN) { wok = (wrow < N); if (!wok) wrow = N - 1; }
    const float* Ap = A + (size_t)(bm + lr) * K + lk;
    const float* Wp = W + (size_t)wrow * K + lk;

    float acc[2][8][4];
#pragma unroll
    for (int mt = 0; mt < 2; mt++)
#pragma unroll
        for (int nt = 0; nt < 8; nt++)
#pragma unroll
            for (int q = 0; q < 4; q++) acc[mt][nt][q] = 0.f;

    const int gq = lane >> 2;   // groupID 0..7
    const int tg = lane & 3;    // thread in group 0..3

    float4 pa0, pa1, pb0, pb1;
    pa0 = *(const float4*)(Ap);
    pa1 = *(const float4*)(Ap + 4);
    if (!CHECKN || wok) {
        pb0 = *(const float4*)(Wp);
        pb1 = *(const float4*)(Wp + 4);
    } else { pb0 = make_float4(0,0,0,0); pb1 = pb0; }

#define GEMM_STAGE(BUF)                                                       \
    {                                                                         \
        float4 ca0 = make_float4(tf32r(pa0.x), tf32r(pa0.y), tf32r(pa0.z), tf32r(pa0.w)); \
        float4 ca1 = make_float4(tf32r(pa1.x), tf32r(pa1.y), tf32r(pa1.z), tf32r(pa1.w)); \
        float4 cb0 = make_float4(tf32r(pb0.x), tf32r(pb0.y), tf32r(pb0.z), tf32r(pb0.w)); \
        float4 cb1 = make_float4(tf32r(pb1.x), tf32r(pb1.y), tf32r(pb1.z), tf32r(pb1.w)); \
        *(float4*)&As[BUF][lr][lk]     = ca0;                                 \
        *(float4*)&As[BUF][lr][lk + 4] = ca1;                                 \
        *(float4*)&Bs[BUF][lr][lk]     = cb0;                                 \
        *(float4*)&Bs[BUF][lr][lk + 4] = cb1;                                 \
    }

#define GEMM_COMPUTE(BUF)                                                     \
    _Pragma("unroll")                                                         \
    for (int ks = 0; ks < 16; ks += 8) {                                      \
        float a[2][4];                                                        \
        float b[8][2];                                                        \
        _Pragma("unroll")                                                     \
        for (int mt = 0; mt < 2; mt++) {                                      \
            int r = wm + mt * 16 + gq;                                        \
            int c = ks + tg;                                                  \
            a[mt][0] = As[BUF][r][c];                                         \
            a[mt][1] = As[BUF][r + 8][c];                                     \
            a[mt][2] = As[BUF][r][c + 4];                                     \
            a[mt][3] = As[BUF][r + 8][c + 4];                                 \
        }                                                                     \
        _Pragma("unroll")                                                     \
        for (int nt = 0; nt < 8; nt++) {                                      \
            int n = wn + nt * 8 + gq;                                         \
            b[nt][0] = Bs[BUF][n][ks + tg];                                   \
            b[nt][1] = Bs[BUF][n][ks + tg + 4];                               \
        }                                                                     \
        _Pragma("unroll")                                                     \
        for (int mt = 0; mt < 2; mt++)                                        \
            _Pragma("unroll")                                                 \
            for (int nt = 0; nt < 8; nt++)                                    \
                mma_tf32(acc[mt][nt], a[mt][0], a[mt][1], a[mt][2], a[mt][3], \
                         b[nt][0], b[nt][1]);                                 \
    }

    GEMM_STAGE(0)
    __syncthreads();

    int buf = 0;
    for (int k0 = 16; k0 < K; k0 += 16) {
        pa0 = *(const float4*)(Ap + k0);
        pa1 = *(const float4*)(Ap + k0 + 4);
        if (!CHECKN || wok) {
            pb0 = *(const float4*)(Wp + k0);
            pb1 = *(const float4*)(Wp + k0 + 4);
        } else { pb0 = make_float4(0,0,0,0); pb1 = pb0; }
        if (buf == 0) { GEMM_COMPUTE(0) GEMM_STAGE(1) }
        else          { GEMM_COMPUTE(1) GEMM_STAGE(0) }
        __syncthreads();
        buf ^= 1;
    }
    if (buf == 0) { GEMM_COMPUTE(0) } else { GEMM_COMPUTE(1) }

    // epilogue
#pragma unroll
    for (int mt = 0; mt < 2; mt++) {
        int r = bm + wm + mt * 16 + gq;
#pragma unroll
        for (int nt = 0; nt < 8; nt++) {
            int cgl = bn + wn + nt * 8 + 2 * tg;
            if (CHECKN && cgl >= N) continue;
            float bv0 = 0.f, bv1 = 0.f;
            if (bias) { bv0 = bias[cgl]; bv1 = bias[cgl + 1]; }
            *(float2*)&C[(size_t)r * N + cgl] =
                make_float2(acc[mt][nt][0] + bv0, acc[mt][nt][1] + bv1);
            *(float2*)&C[(size_t)(r + 8) * N + cgl] =
                make_float2(acc[mt][nt][2] + bv0, acc[mt][nt][3] + bv1);
        }
    }
#undef GEMM_STAGE
#undef GEMM_COMPUTE
}

// ---------------- tensor-core LSTM step --------------------------------------
// Grid (32 j-strips of 16, 4 b-tiles of 64) = 128 blocks, 256 threads.
__global__ __launch_bounds__(256, 1)
void lstm_step_tc(const float* __restrict__ Xg_t,   // (B, 4H), biases included
                  const float* __restrict__ w_hh,   // (4H, H)
                  const float* __restrict__ h_in,   // (B, H)
                  float* __restrict__ h_out,        // (B, H)
                  const int* __restrict__ lengths,
                  int t) {
    __shared__ __align__(16) float hs[2][64][20];
    __shared__ __align__(16) float ws[2][64][20];
    __shared__ __align__(8)  float ps[64][68];

    const int tid = threadIdx.x;
    const int lane = tid & 31;
    const int wid = tid >> 5;
    const int wm = (wid & 1) * 32;     // 2 m-halves of 32 rows
    const int wn = (wid >> 1) * 16;    // 4 n-quads of 16 cols
    const int j0 = blockIdx.x * 16;
    const int b0 = blockIdx.y * 64;

    const int row = tid >> 2;
    const int kq = (tid & 3) * 4;
    const float* hp = h_in + (size_t)(b0 + row) * H_ + kq;
    const int gsel = row >> 4;               // gate 0..3
    const int jl = row & 15;
    const float* wp = w_hh + (size_t)(gsel * H_ + j0 + jl) * H_ + kq;

    const int gq = lane >> 2;
    const int tg = lane & 3;

    float acc[2][2][4];
#pragma unroll
    for (int mt = 0; mt < 2; mt++)
#pragma unroll
        for (int nt = 0; nt < 2; nt++)
#pragma unroll
            for (int q = 0; q < 4; q++) acc[mt][nt][q] = 0.f;

    float4 ph, pw;
    ph = *(const float4*)(hp);
    pw = *(const float4*)(wp);

#define LSTM_STAGE(BUF)                                                       \
    {                                                                         \
        *(float4*)&hs[BUF][row][kq] =                                         \
            make_float4(tf32r(ph.x), tf32r(ph.y), tf32r(ph.z), tf32r(ph.w));  \
        *(float4*)&ws[BUF][row][kq] =                                         \
            make_float4(tf32r(pw.x), tf32r(pw.y), tf32r(pw.z), tf32r(pw.w));  \
    }

#define LSTM_COMPUTE(BUF)                                                     \
    _Pragma("unroll")                                                         \
    for (int ks = 0; ks < 16; ks += 8) {                                      \
        float a[2][4];                                                        \
        float b[2][2];                                                        \
        _Pragma("unroll")                                                     \
        for (int mt = 0; mt < 2; mt++) {                                      \
            int r = wm + mt * 16 + gq;                                        \
            int c = ks + tg;                                                  \
            a[mt][0] = hs[BUF][r][c];                                         \
            a[mt][1] = hs[BUF][r + 8][c];                                     \
            a[mt][2] = hs[BUF][r][c + 4];                                     \
            a[mt][3] = hs[BUF][r + 8][c + 4];                                 \
        }                                                                     \
        _Pragma("unroll")                                                     \
        for (int nt = 0; nt < 2; nt++) {                                      \
            int n = wn + nt * 8 + gq;                                         \
            b[nt][0] = ws[BUF][n][ks + tg];                                   \
            b[nt][1] = ws[BUF][n][ks + tg + 4];                               \
        }                                                                     \
        _Pragma("unroll")                                                     \
        for (int mt = 0; mt < 2; mt++)                                        \
            _Pragma("unroll")                                                 \
            for (int nt = 0; nt < 2; nt++)                                    \
                mma_tf32(acc[mt][nt], a[mt][0], a[mt][1], a[mt][2], a[mt][3], \
                         b[nt][0], b[nt][1]);                                 \
    }

    LSTM_STAGE(0)
    __syncthreads();

    int buf = 0;
    for (int k0 = 16; k0 < H_; k0 += 16) {
        ph = *(const float4*)(hp + k0);
        pw = *(const float4*)(wp + k0);
        if (buf == 0) { LSTM_COMPUTE(0) LSTM_STAGE(1) }
        else          { LSTM_COMPUTE(1) LSTM_STAGE(0) }
        __syncthreads();
        buf ^= 1;
    }
    if (buf == 0) { LSTM_COMPUTE(0) } else { LSTM_COMPUTE(1) }

    // preacts -> shared
#pragma unroll
    for (int mt = 0; mt < 2; mt++) {
        int r = wm + mt * 16 + gq;
#pragma unroll
        for (int nt = 0; nt < 2; nt++) {
            int c = wn + nt * 8 + 2 * tg;
            *(float2*)&ps[r][c] = make_float2(acc[mt][nt][0], acc[mt][nt][1]);
            *(float2*)&ps[r + 8][c] = make_float2(acc[mt][nt][2], acc[mt][nt][3]);
        }
    }
    __syncthreads();

    // gate epilogue: 64 b x 16 j cells, 4 per thread
#pragma unroll
    for (int p = 0; p < 4; p++) {
        int idx = tid + p * 256;
        int bl = idx & 63;
        int jloc = idx >> 6;        // 0..15
        int b = b0 + bl;
        int j = j0 + jloc;
        const float* xg = Xg_t + (size_t)b * G4_;
        float gi = sigmoidf_(ps[bl][jloc]      + xg[j]);
        float gf = sigmoidf_(ps[bl][16 + jloc] + xg[H_ + j]);
        float gg = tanhf(    ps[bl][32 + jloc] + xg[2 * H_ + j]);
        float go = sigmoidf_(ps[bl][48 + jloc] + xg[3 * H_ + j]);
        float cn = gf * g_c[b * H_ + j] + gi * gg;
        g_c[b * H_ + j] = cn;
        float hn = go * tanhf(cn);
        h_out[b * H_ + j] = hn;
        g_lstm_out[(size_t)(b * T_ + t) * H_ + j] = (t < lengths[b]) ? hn : 0.f;
    }
#undef LSTM_STAGE
#undef LSTM_COMPUTE
}

// ---------------- attention: one block per (b, head) ------------------------
__global__ __launch_bounds__(256)
void attention_kernel(const float* __restrict__ Q,
                      const float* __restrict__ Kmat,
                      const float* __restrict__ V,
                      const int* __restrict__ lengths,
                      float* __restrict__ Wout) {
    __shared__ float qs[64 * 64];
    __shared__ float ks[64 * 64];
    __shared__ float ss[64 * 64];
    const int b = blockIdx.x, nh = blockIdx.y;
    const int tid = threadIdx.x;
    const int len = lengths[b];
    const size_t base = ((size_t)b * 64) * 512 + nh * 64;

#pragma unroll
    for (int l = 0; l < 4; l++) {
        int fidx = tid + (l << 8);
        int r = fidx & 63, c4 = fidx >> 6;
        float4 qv = *(const float4*)(Q + base + (size_t)r * 512 + c4 * 4);
        float4 kv = *(const float4*)(Kmat + base + (size_t)r * 512 + c4 * 4);
        qs[(c4 * 4 + 0) * 64 + r] = qv.x; qs[(c4 * 4 + 1) * 64 + r] = qv.y;
        qs[(c4 * 4 + 2) * 64 + r] = qv.z; qs[(c4 * 4 + 3) * 64 + r] = qv.w;
        ks[(c4 * 4 + 0) * 64 + r] = kv.x; ks[(c4 * 4 + 1) * 64 + r] = kv.y;
        ks[(c4 * 4 + 2) * 64 + r] = kv.z; ks[(c4 * 4 + 3) * 64 + r] = kv.w;
    }
    __syncthreads();

    const int tx = tid & 15, ty = tid >> 4;
    const int r0 = ty * 4, c0 = tx * 4;
    float acc[4][4];
#pragma unroll
    for (int i = 0; i < 4; i++)
#pragma unroll
        for (int j = 0; j < 4; j++) acc[i][j] = 0.f;

#pragma unroll 8
    for (int k = 0; k < 64; k++) {
        float4 aq = *(const float4*)&qs[k * 64 + r0];
        float4 bk = *(const float4*)&ks[k * 64 + c0];
        float a[4] = {aq.x, aq.y, aq.z, aq.w};
        float bb[4] = {bk.x, bk.y, bk.z, bk.w};
#pragma unroll
        for (int i = 0; i < 4; i++)
#pragma unroll
            for (int j = 0; j < 4; j++) acc[i][j] += a[i] * bb[j];
    }
#pragma unroll
    for (int i = 0; i < 4; i++)
#pragma unroll
        for (int j = 0; j < 4; j++) {
            int c = c0 + j;
            ss[(r0 + i) * 64 + c] = (c < len) ? acc[i][j] * 0.125f : -1e30f;
        }
    __syncthreads();

    float* vs = qs;
#pragma unroll
    for (int l = 0; l < 4; l++) {
        int fidx = tid + (l << 8);
        int r = fidx >> 4, c4 = fidx & 15;
        ((float4*)vs)[fidx] = *(const float4*)(V + base + (size_t)r * 512 + c4 * 4);
    }
    if (tid < 64) {
        float m = -1e30f;
#pragma unroll 8
        for (int c = 0; c < 64; c++) m = fmaxf(m, ss[tid * 64 + c]);
        float s = 0.f;
#pragma unroll 8
        for (int c = 0; c < 64; c++) {
            float e = expf(ss[tid * 64 + c] - m);
            ss[tid * 64 + c] = e;
            s += e;
        }
        float inv = 1.f / s;
#pragma unroll 8
        for (int c = 0; c < 64; c++) ss[tid * 64 + c] *= inv;
    }
    __syncthreads();

    float o[4][4];
#pragma unroll
    for (int i = 0; i < 4; i++)
#pragma unroll
        for (int j = 0; j < 4; j++) o[i][j] = 0.f;
#pragma unroll 8
    for (int k = 0; k < 64; k++) {
        float a[4];
#pragma unroll
        for (int i = 0; i < 4; i++) a[i] = ss[(r0 + i) * 64 + k];
        float4 vv4 = *(const float4*)&vs[k * 64 + c0];
        float vv[4] = {vv4.x, vv4.y, vv4.z, vv4.w};
#pragma unroll
        for (int i = 0; i < 4; i++)
#pragma unroll
            for (int j = 0; j < 4; j++) o[i][j] += a[i] * vv[j];
    }
#pragma unroll
    for (int i = 0; i < 4; i++) {
        float4 ov = make_float4(o[i][0], o[i][1], o[i][2], o[i][3]);
        *(float4*)(Wout + base + (size_t)(r0 + i) * 512 + c0) = ov;
    }
}

// ---------------- fused meanpool + hidden_to_embedding ----------------------
// One block per batch element b. pooled = mean_t mho[b,t,:]; ae = pooled @ w_h2e^T + b.
__global__ __launch_bounds__(128)
void pool_h2e_kernel(const float* __restrict__ w_h2e,
                     const float* __restrict__ b_h2e) {
    __shared__ float sp[H_];
    const int b = blockIdx.x;
    const int tid = threadIdx.x;   // 128 threads
    // each thread accumulates 4 columns: j = tid*4 .. tid*4+3
    float s0 = 0.f, s1 = 0.f, s2 = 0.f, s3 = 0.f;
    const float* src = g_mho + (size_t)b * 64 * H_ + tid * 4;
#pragma unroll 8
    for (int t = 0; t < 64; t++) {
        float4 v = *(const float4*)(src + (size_t)t * H_);
        s0 += v.x; s1 += v.y; s2 += v.z; s3 += v.w;
    }
    sp[tid * 4 + 0] = s0 * (1.f / 64.f);
    sp[tid * 4 + 1] = s1 * (1.f / 64.f);
    sp[tid * 4 + 2] = s2 * (1.f / 64.f);
    sp[tid * 4 + 3] = s3 * (1.f / 64.f);
    __syncthreads();
    float acc = b_h2e[tid];
    const float* wr = w_h2e + (size_t)tid * H_;
#pragma unroll 8
    for (int k = 0; k < H_; k++) acc += sp[k] * wr[k];
    g_ae[b * E_ + tid] = acc;
}

// ---------------- entry point -----------------------------------------------
extern "C" void kernel_launch(void* const* d_in, const int* in_sizes, int n_in,
                              void* d_out, int out_size) {
    const int*   x       = (const int*)d_in[0];
    const int*   lengths = (const int*)d_in[1];
    const float* emb     = (const float*)d_in[2];
    const float* w_ih    = (const float*)d_in[3];
    const float* w_hh    = (const float*)d_in[4];
    const float* b_ih    = (const float*)d_in[5];
    const float* b_hh    = (const float*)d_in[6];
    const float* wq      = (const float*)d_in[7];
    const float* bq      = (const float*)d_in[8];
    const float* wk      = (const float*)d_in[9];
    const float* bk      = (const float*)d_in[10];
    const float* wv      = (const float*)d_in[11];
    const float* bv      = (const float*)d_in[12];
    const float* wo      = (const float*)d_in[13];
    const float* bo      = (const float*)d_in[14];
    const float* w_h2e   = (const float*)d_in[15];
    const float* b_h2e   = (const float*)d_in[16];
    float* out = (float*)d_out;

    float *p_embs, *p_bsum, *p_Xg, *p_h, *p_lo, *p_Q, *p_K, *p_V, *p_w, *p_mho, *p_ae;
    cudaGetSymbolAddress((void**)&p_embs, g_embs);
    cudaGetSymbolAddress((void**)&p_bsum, g_bsum);
    cudaGetSymbolAddress((void**)&p_Xg,   g_Xg);
    cudaGetSymbolAddress((void**)&p_h,    g_hbuf);
    cudaGetSymbolAddress((void**)&p_lo,   g_lstm_out);
    cudaGetSymbolAddress((void**)&p_Q,    g_Q);
    cudaGetSymbolAddress((void**)&p_K,    g_K);
    cudaGetSymbolAddress((void**)&p_V,    g_V);
    cudaGetSymbolAddress((void**)&p_w,    g_wout);
    cudaGetSymbolAddress((void**)&p_mho,  g_mho);
    cudaGetSymbolAddress((void**)&p_ae,   g_ae);
    float* p_h0 = p_h;
    float* p_h1 = p_h + B_ * H_;

    zero_init_kernel<<<(B_ * H_ + 255) / 256, 256>>>();
    bias_sum_kernel<<<(G4_ + 255) / 256, 256>>>(b_ih, b_hh);
    gather_square_kernel<<<(TB_ * E_ / 4 + 255) / 256, 256>>>(x, emb);

    // Xg = embs @ w_ih^T + (b_ih + b_hh)
    gemm_tf32<false><<<dim3(G4_ / 128, TB_ / 128), 256>>>(p_embs, w_ih, p_bsum, p_Xg, TB_, G4_, E_);

    // LSTM recurrence (tensor cores, fused gates)
    for (int t = 0; t < T_; t++) {
        const float* hin = (t & 1) ? p_h1 : p_h0;
        float* hout      = (t & 1) ? p_h0 : p_h1;
        lstm_step_tc<<<dim3(H_ / 16, B_ / 64), 256>>>(
            p_Xg + (size_t)t * B_ * G4_, w_hh, hin, hout, lengths, t);
    }

    // QKV projections
    gemm_tf32<false><<<dim3(H_ / 128, TB_ / 128), 256>>>(p_lo, wq, bq, p_Q, TB_, H_, H_);
    gemm_tf32<false><<<dim3(H_ / 128, TB_ / 128), 256>>>(p_lo, wk, bk, p_K, TB_, H_, H_);
    gemm_tf32<false><<<dim3(H_ / 128, TB_ / 128), 256>>>(p_lo, wv, bv, p_V, TB_, H_, H_);

    attention_kernel<<<dim3(B_, NH_), 256>>>(p_Q, p_K, p_V, lengths, p_w);

    // output projection
    gemm_tf32<false><<<dim3(H_ / 128, TB_ / 128), 256>>>(p_w, wo, bo, p_mho, TB_, H_, H_);

    // fused mean-pool + hidden_to_embedding
    pool_h2e_kernel<<<B_, 128>>>(w_h2e, b_h2e);

    // final scores = ae @ emb^T
    gemm_tf32<true><<<dim3((NITEMS + 127) / 128, B_ / 128), 256>>>(p_ae, emb, nullptr, out, B_, NITEMS, E_);
}

// round 6
// speedup vs baseline: 2.1867x; 1.2528x over previous
#include <cuda_runtime.h>
#include <math.h>
#include <stdint.h>

// Problem constants
constexpr int T_ = 64;
constexpr int B_ = 256;
constexpr int NITEMS = 100000;
constexpr int E_ = 128;
constexpr int H_ = 512;
constexpr int NH_ = 8;
constexpr int G4_ = 4 * H_;   // 2048
constexpr int TB_ = T_ * B_;  // 16384

// ---------------- scratch (device globals) ----------------------------------
__device__ float g_embs[TB_ * E_];
__device__ float g_bsum[G4_];
__device__ float g_Xg[TB_ * G4_];
__device__ float g_hseq[(T_ + 1) * B_ * H_];   // h per step (fresh buffer/step)
__device__ float g_c[B_ * H_];
__device__ float g_lstm_out[TB_ * H_];         // (B,T,H)
__device__ float g_Q[TB_ * H_];
__device__ float g_K[TB_ * H_];
__device__ float g_V[TB_ * H_];
__device__ float g_wout[TB_ * H_];
__device__ float g_mho[TB_ * H_];
__device__ float g_ae[B_ * E_];
__device__ unsigned int g_bar;

// ---------------- helpers ----------------------------------------------------
__device__ __forceinline__ float tf32r(float x) {
    uint32_t u;
    asm("cvt.rna.tf32.f32 %0, %1;" : "=r"(u) : "f"(x));
    return __uint_as_float(u);
}

__device__ __forceinline__ void mma_tf32(float c[4],
                                         float a0, float a1, float a2, float a3,
                                         float b0, float b1) {
    asm volatile(
        "mma.sync.aligned.m16n8k8.row.col.f32.tf32.tf32.f32 "
        "{%0,%1,%2,%3},{%4,%5,%6,%7},{%8,%9},{%0,%1,%2,%3};"
        : "+f"(c[0]), "+f"(c[1]), "+f"(c[2]), "+f"(c[3])
        : "r"(__float_as_uint(a0)), "r"(__float_as_uint(a1)),
          "r"(__float_as_uint(a2)), "r"(__float_as_uint(a3)),
          "r"(__float_as_uint(b0)), "r"(__float_as_uint(b1)));
}

__device__ __forceinline__ float sigmoidf_(float x) {
    return 1.f / (1.f + expf(-x));
}

// ---------------- small kernels ---------------------------------------------
__global__ void zero_init_kernel() {
    int i = blockIdx.x * blockDim.x + threadIdx.x;
    if (i < B_ * H_) { g_hseq[i] = 0.f; g_c[i] = 0.f; }
    if (i == 0) g_bar = 0u;
}

__global__ void bias_sum_kernel(const float* __restrict__ b_ih,
                                const float* __restrict__ b_hh) {
    int i = blockIdx.x * blockDim.x + threadIdx.x;
    if (i < G4_) g_bsum[i] = b_ih[i] + b_hh[i];
}

__global__ void gather_square_kernel(const int* __restrict__ x,
                                     const float* __restrict__ emb) {
    int fi = blockIdx.x * blockDim.x + threadIdx.x;
    int row = fi >> 5;
    int c4  = fi & 31;
    int id = x[row];
    float4 v = ((const float4*)(emb + (size_t)id * E_))[c4];
    float4 o;
    o.x = v.x * v.x; o.y = v.y * v.y; o.z = v.z * v.z; o.w = v.w * v.w;
    ((float4*)g_embs)[fi] = o;
}

// ---------------- tf32 tensor-core GEMM: C = A(MxK) W(NxK)^T + bias ----------
template<bool CHECKN>
__global__ __launch_bounds__(256, 2)
void gemm_tf32(const float* __restrict__ A, const float* __restrict__ W,
               const float* __restrict__ bias, float* __restrict__ C,
               int M, int N, int K) {
    __shared__ __align__(16) float As[2][128][20];
    __shared__ __align__(16) float Bs[2][128][20];

    const int tid = threadIdx.x;
    const int lane = tid & 31;
    const int wid = tid >> 5;
    const int wm = (wid & 3) * 32;
    const int wn = (wid >> 2) * 64;
    const int bm = blockIdx.y * 128;
    const int bn = blockIdx.x * 128;
    const int lr = tid >> 1;            // 0..127
    const int lk = (tid & 1) * 8;       // 0 or 8

    int wrow = bn + lr;
    bool wok = true;
    if (CHECKN) { wok = (wrow < N); if (!wok) wrow = N - 1; }
    const float* Ap = A + (size_t)(bm + lr) * K + lk;
    const float* Wp = W + (size_t)wrow * K + lk;

    float acc[2][8][4];
#pragma unroll
    for (int mt = 0; mt < 2; mt++)
#pragma unroll
        for (int nt = 0; nt < 8; nt++)
#pragma unroll
            for (int q = 0; q < 4; q++) acc[mt][nt][q] = 0.f;

    const int gq = lane >> 2;   // groupID 0..7
    const int tg = lane & 3;    // thread in group 0..3

    float4 pa0, pa1, pb0, pb1;
    pa0 = *(const float4*)(Ap);
    pa1 = *(const float4*)(Ap + 4);
    if (!CHECKN || wok) {
        pb0 = *(const float4*)(Wp);
        pb1 = *(const float4*)(Wp + 4);
    } else { pb0 = make_float4(0,0,0,0); pb1 = pb0; }

#define GEMM_STAGE(BUF)                                                       \
    {                                                                         \
        float4 ca0 = make_float4(tf32r(pa0.x), tf32r(pa0.y), tf32r(pa0.z), tf32r(pa0.w)); \
        float4 ca1 = make_float4(tf32r(pa1.x), tf32r(pa1.y), tf32r(pa1.z), tf32r(pa1.w)); \
        float4 cb0 = make_float4(tf32r(pb0.x), tf32r(pb0.y), tf32r(pb0.z), tf32r(pb0.w)); \
        float4 cb1 = make_float4(tf32r(pb1.x), tf32r(pb1.y), tf32r(pb1.z), tf32r(pb1.w)); \
        *(float4*)&As[BUF][lr][lk]     = ca0;                                 \
        *(float4*)&As[BUF][lr][lk + 4] = ca1;                                 \
        *(float4*)&Bs[BUF][lr][lk]     = cb0;                                 \
        *(float4*)&Bs[BUF][lr][lk + 4] = cb1;                                 \
    }

#define GEMM_COMPUTE(BUF)                                                     \
    _Pragma("unroll")                                                         \
    for (int ks = 0; ks < 16; ks += 8) {                                      \
        float a[2][4];                                                        \
        float b[8][2];                                                        \
        _Pragma("unroll")                                                     \
        for (int mt = 0; mt < 2; mt++) {                                      \
            int r = wm + mt * 16 + gq;                                        \
            int c = ks + tg;                                                  \
            a[mt][0] = As[BUF][r][c];                                         \
            a[mt][1] = As[BUF][r + 8][c];                                     \
            a[mt][2] = As[BUF][r][c + 4];                                     \
            a[mt][3] = As[BUF][r + 8][c + 4];                                 \
        }                                                                     \
        _Pragma("unroll")                                                     \
        for (int nt = 0; nt < 8; nt++) {                                      \
            int n = wn + nt * 8 + gq;                                         \
            b[nt][0] = Bs[BUF][n][ks + tg];                                   \
            b[nt][1] = Bs[BUF][n][ks + tg + 4];                               \
        }                                                                     \
        _Pragma("unroll")                                                     \
        for (int mt = 0; mt < 2; mt++)                                        \
            _Pragma("unroll")                                                 \
            for (int nt = 0; nt < 8; nt++)                                    \
                mma_tf32(acc[mt][nt], a[mt][0], a[mt][1], a[mt][2], a[mt][3], \
                         b[nt][0], b[nt][1]);                                 \
    }

    GEMM_STAGE(0)
    __syncthreads();

    int buf = 0;
    for (int k0 = 16; k0 < K; k0 += 16) {
        pa0 = *(const float4*)(Ap + k0);
        pa1 = *(const float4*)(Ap + k0 + 4);
        if (!CHECKN || wok) {
            pb0 = *(const float4*)(Wp + k0);
            pb1 = *(const float4*)(Wp + k0 + 4);
        } else { pb0 = make_float4(0,0,0,0); pb1 = pb0; }
        if (buf == 0) { GEMM_COMPUTE(0) GEMM_STAGE(1) }
        else          { GEMM_COMPUTE(1) GEMM_STAGE(0) }
        __syncthreads();
        buf ^= 1;
    }
    if (buf == 0) { GEMM_COMPUTE(0) } else { GEMM_COMPUTE(1) }

    // epilogue
#pragma unroll
    for (int mt = 0; mt < 2; mt++) {
        int r = bm + wm + mt * 16 + gq;
#pragma unroll
        for (int nt = 0; nt < 8; nt++) {
            int cgl = bn + wn + nt * 8 + 2 * tg;
            if (CHECKN && cgl >= N) continue;
            float bv0 = 0.f, bv1 = 0.f;
            if (bias) { bv0 = bias[cgl]; bv1 = bias[cgl + 1]; }
            *(float2*)&C[(size_t)r * N + cgl] =
                make_float2(acc[mt][nt][0] + bv0, acc[mt][nt][1] + bv1);
            *(float2*)&C[(size_t)(r + 8) * N + cgl] =
                make_float2(acc[mt][nt][2] + bv0, acc[mt][nt][3] + bv1);
        }
    }
#undef GEMM_STAGE
#undef GEMM_COMPUTE
}

// ---------------- persistent tensor-core LSTM --------------------------------
// 128 resident blocks (32 j-strips x 4 b-tiles), 256 threads.
// W slice cached in dynamic smem once; 64 steps with global barrier.
constexpr int WS_STR = 516;                 // stride-516 -> conflict-free frags
constexpr int WS_FLOATS = 64 * WS_STR;      // 33024
constexpr int HS_FLOATS = 64 * 36;          // per buffer
constexpr int LSTM_SMEM_BYTES = (WS_FLOATS + 2 * HS_FLOATS + 64 * 68) * 4;

__global__ __launch_bounds__(256, 1)
void lstm_persistent(const float* __restrict__ Xg,      // (T,B,4H)
                     const float* __restrict__ w_hh,    // (4H,H)
                     const int* __restrict__ lengths) {
    extern __shared__ __align__(16) float dsm[];
    float* ws  = dsm;                          // [64][516]
    float* hsA = dsm + WS_FLOATS;              // [64][36]
    float* hsB = hsA + HS_FLOATS;              // [64][36]
    float* ps  = hsB + HS_FLOATS;              // [64][68]

    const int tid = threadIdx.x;
    const int lane = tid & 31;
    const int wid = tid >> 5;
    const int wm = (wid & 1) * 32;
    const int wn = (wid >> 1) * 16;
    const int j0 = (blockIdx.x & 31) * 16;
    const int b0 = (blockIdx.x >> 5) * 64;

    const int gq = lane >> 2;
    const int tg = lane & 3;

    // ---- load W slice once (rows n: gate = n>>4, jl = n&15) ----
    for (int idx = tid; idx < 64 * 128; idx += 256) {
        int n = idx >> 7;
        int k4 = (idx & 127) * 4;
        int g = n >> 4, jl = n & 15;
        float4 v = *(const float4*)(w_hh + (size_t)(g * H_ + j0 + jl) * H_ + k4);
        float* dst = ws + n * WS_STR + k4;
        dst[0] = tf32r(v.x); dst[1] = tf32r(v.y);
        dst[2] = tf32r(v.z); dst[3] = tf32r(v.w);
    }
    __syncthreads();

    // h staging indices: row 0..63, kq in {0,8,16,24}
    const int row = tid >> 2;
    const int kq = (tid & 3) * 8;

    int len4[4];
#pragma unroll
    for (int p = 0; p < 4; p++) len4[p] = lengths[b0 + ((tid + p * 256) & 63)];

#define PSTAGE(HS)                                                            \
    {                                                                         \
        float* d = (HS) + row * 36 + kq;                                      \
        d[0] = tf32r(q0.x); d[1] = tf32r(q0.y);                               \
        d[2] = tf32r(q0.z); d[3] = tf32r(q0.w);                               \
        d[4] = tf32r(q1.x); d[5] = tf32r(q1.y);                               \
        d[6] = tf32r(q1.z); d[7] = tf32r(q1.w);                               \
    }

#define PCOMPUTE(HS, CH)                                                      \
    _Pragma("unroll")                                                         \
    for (int ks = 0; ks < 32; ks += 8) {                                      \
        float a[2][4];                                                        \
        float bf[2][2];                                                       \
        _Pragma("unroll")                                                     \
        for (int mt = 0; mt < 2; mt++) {                                      \
            int r = wm + mt * 16 + gq;                                        \
            int cc = ks + tg;                                                 \
            a[mt][0] = (HS)[r * 36 + cc];                                     \
            a[mt][1] = (HS)[(r + 8) * 36 + cc];                               \
            a[mt][2] = (HS)[r * 36 + cc + 4];                                 \
            a[mt][3] = (HS)[(r + 8) * 36 + cc + 4];                           \
        }                                                                     \
        _Pragma("unroll")                                                     \
        for (int nt = 0; nt < 2; nt++) {                                      \
            int n = wn + nt * 8 + gq;                                         \
            bf[nt][0] = ws[n * WS_STR + (CH) * 32 + ks + tg];                 \
            bf[nt][1] = ws[n * WS_STR + (CH) * 32 + ks + tg + 4];             \
        }                                                                     \
        _Pragma("unroll")                                                     \
        for (int mt = 0; mt < 2; mt++)                                        \
            _Pragma("unroll")                                                 \
            for (int nt = 0; nt < 2; nt++)                                    \
                mma_tf32(acc[mt][nt], a[mt][0], a[mt][1], a[mt][2], a[mt][3], \
                         bf[nt][0], bf[nt][1]);                               \
    }

    for (int t = 0; t < T_; t++) {
        const float* hin = g_hseq + (size_t)t * B_ * H_ + (size_t)(b0 + row) * H_ + kq;
        float acc[2][2][4];
#pragma unroll
        for (int mt = 0; mt < 2; mt++)
#pragma unroll
            for (int nt = 0; nt < 2; nt++)
#pragma unroll
                for (int q = 0; q < 4; q++) acc[mt][nt][q] = 0.f;

        float4 q0 = *(const float4*)(hin);
        float4 q1 = *(const float4*)(hin + 4);
        PSTAGE(hsA)
        __syncthreads();

        for (int ch = 1; ch < 16; ch++) {
            q0 = *(const float4*)(hin + ch * 32);
            q1 = *(const float4*)(hin + ch * 32 + 4);
            if (ch & 1) { PCOMPUTE(hsA, ch - 1) PSTAGE(hsB) }
            else        { PCOMPUTE(hsB, ch - 1) PSTAGE(hsA) }
            __syncthreads();
        }
        PCOMPUTE(hsB, 15)

        // preacts -> shared
#pragma unroll
        for (int mt = 0; mt < 2; mt++) {
            int r = wm + mt * 16 + gq;
#pragma unroll
            for (int nt = 0; nt < 2; nt++) {
                int c = wn + nt * 8 + 2 * tg;
                *(float2*)&ps[r * 68 + c] = make_float2(acc[mt][nt][0], acc[mt][nt][1]);
                *(float2*)&ps[(r + 8) * 68 + c] = make_float2(acc[mt][nt][2], acc[mt][nt][3]);
            }
        }
        __syncthreads();

        // gate epilogue
        const float* Xg_t = Xg + (size_t)t * B_ * G4_;
        float* hout = g_hseq + (size_t)(t + 1) * B_ * H_;
#pragma unroll
        for (int p = 0; p < 4; p++) {
            int idx = tid + p * 256;
            int bl = idx & 63;
            int jloc = idx >> 6;
            int b = b0 + bl;
            int j = j0 + jloc;
            const float* xg = Xg_t + (size_t)b * G4_;
            float gi = sigmoidf_(ps[bl * 68 + jloc]      + xg[j]);
            float gf = sigmoidf_(ps[bl * 68 + 16 + jloc] + xg[H_ + j]);
            float gg = tanhf(    ps[bl * 68 + 32 + jloc] + xg[2 * H_ + j]);
            float go = sigmoidf_(ps[bl * 68 + 48 + jloc] + xg[3 * H_ + j]);
            float cn = gf * g_c[b * H_ + j] + gi * gg;
            g_c[b * H_ + j] = cn;
            float hn = go * tanhf(cn);
            hout[(size_t)b * H_ + j] = hn;
            g_lstm_out[(size_t)(b * T_ + t) * H_ + j] = (t < len4[p]) ? hn : 0.f;
        }

        // global barrier (release h writes, then arrive+spin)
        __syncthreads();
        if (tid == 0) {
            __threadfence();
            atomicAdd(&g_bar, 1u);
            unsigned target = 128u * (unsigned)(t + 1);
            volatile unsigned* vb = &g_bar;
            while (*vb < target) { }
        }
        __syncthreads();
    }
#undef PSTAGE
#undef PCOMPUTE
}

// ---------------- attention: one block per (b, head) ------------------------
__global__ __launch_bounds__(256)
void attention_kernel(const float* __restrict__ Q,
                      const float* __restrict__ Kmat,
                      const float* __restrict__ V,
                      const int* __restrict__ lengths,
                      float* __restrict__ Wout) {
    __shared__ float qs[64 * 64];
    __shared__ float ks[64 * 64];
    __shared__ float ss[64 * 64];
    const int b = blockIdx.x, nh = blockIdx.y;
    const int tid = threadIdx.x;
    const int len = lengths[b];
    const size_t base = ((size_t)b * 64) * 512 + nh * 64;

#pragma unroll
    for (int l = 0; l < 4; l++) {
        int fidx = tid + (l << 8);
        int r = fidx & 63, c4 = fidx >> 6;
        float4 qv = *(const float4*)(Q + base + (size_t)r * 512 + c4 * 4);
        float4 kv = *(const float4*)(Kmat + base + (size_t)r * 512 + c4 * 4);
        qs[(c4 * 4 + 0) * 64 + r] = qv.x; qs[(c4 * 4 + 1) * 64 + r] = qv.y;
        qs[(c4 * 4 + 2) * 64 + r] = qv.z; qs[(c4 * 4 + 3) * 64 + r] = qv.w;
        ks[(c4 * 4 + 0) * 64 + r] = kv.x; ks[(c4 * 4 + 1) * 64 + r] = kv.y;
        ks[(c4 * 4 + 2) * 64 + r] = kv.z; ks[(c4 * 4 + 3) * 64 + r] = kv.w;
    }
    __syncthreads();

    const int tx = tid & 15, ty = tid >> 4;
    const int r0 = ty * 4, c0 = tx * 4;
    float acc[4][4];
#pragma unroll
    for (int i = 0; i < 4; i++)
#pragma unroll
        for (int j = 0; j < 4; j++) acc[i][j] = 0.f;

#pragma unroll 8
    for (int k = 0; k < 64; k++) {
        float4 aq = *(const float4*)&qs[k * 64 + r0];
        float4 bk = *(const float4*)&ks[k * 64 + c0];
        float a[4] = {aq.x, aq.y, aq.z, aq.w};
        float bb[4] = {bk.x, bk.y, bk.z, bk.w};
#pragma unroll
        for (int i = 0; i < 4; i++)
#pragma unroll
            for (int j = 0; j < 4; j++) acc[i][j] += a[i] * bb[j];
    }
#pragma unroll
    for (int i = 0; i < 4; i++)
#pragma unroll
        for (int j = 0; j < 4; j++) {
            int c = c0 + j;
            ss[(r0 + i) * 64 + c] = (c < len) ? acc[i][j] * 0.125f : -1e30f;
        }
    __syncthreads();

    float* vs = qs;
#pragma unroll
    for (int l = 0; l < 4; l++) {
        int fidx = tid + (l << 8);
        int r = fidx >> 4, c4 = fidx & 15;
        ((float4*)vs)[fidx] = *(const float4*)(V + base + (size_t)r * 512 + c4 * 4);
    }
    if (tid < 64) {
        float m = -1e30f;
#pragma unroll 8
        for (int c = 0; c < 64; c++) m = fmaxf(m, ss[tid * 64 + c]);
        float s = 0.f;
#pragma unroll 8
        for (int c = 0; c < 64; c++) {
            float e = expf(ss[tid * 64 + c] - m);
            ss[tid * 64 + c] = e;
            s += e;
        }
        float inv = 1.f / s;
#pragma unroll 8
        for (int c = 0; c < 64; c++) ss[tid * 64 + c] *= inv;
    }
    __syncthreads();

    float o[4][4];
#pragma unroll
    for (int i = 0; i < 4; i++)
#pragma unroll
        for (int j = 0; j < 4; j++) o[i][j] = 0.f;
#pragma unroll 8
    for (int k = 0; k < 64; k++) {
        float a[4];
#pragma unroll
        for (int i = 0; i < 4; i++) a[i] = ss[(r0 + i) * 64 + k];
        float4 vv4 = *(const float4*)&vs[k * 64 + c0];
        float vv[4] = {vv4.x, vv4.y, vv4.z, vv4.w};
#pragma unroll
        for (int i = 0; i < 4; i++)
#pragma unroll
            for (int j = 0; j < 4; j++) o[i][j] += a[i] * vv[j];
    }
#pragma unroll
    for (int i = 0; i < 4; i++) {
        float4 ov = make_float4(o[i][0], o[i][1], o[i][2], o[i][3]);
        *(float4*)(Wout + base + (size_t)(r0 + i) * 512 + c0) = ov;
    }
}

// ---------------- fused meanpool + hidden_to_embedding ----------------------
__global__ __launch_bounds__(128)
void pool_h2e_kernel(const float* __restrict__ w_h2e,
                     const float* __restrict__ b_h2e) {
    __shared__ float sp[H_];
    const int b = blockIdx.x;
    const int tid = threadIdx.x;
    float s0 = 0.f, s1 = 0.f, s2 = 0.f, s3 = 0.f;
    const float* src = g_mho + (size_t)b * 64 * H_ + tid * 4;
#pragma unroll 8
    for (int t = 0; t < 64; t++) {
        float4 v = *(const float4*)(src + (size_t)t * H_);
        s0 += v.x; s1 += v.y; s2 += v.z; s3 += v.w;
    }
    sp[tid * 4 + 0] = s0 * (1.f / 64.f);
    sp[tid * 4 + 1] = s1 * (1.f / 64.f);
    sp[tid * 4 + 2] = s2 * (1.f / 64.f);
    sp[tid * 4 + 3] = s3 * (1.f / 64.f);
    __syncthreads();
    float acc = b_h2e[tid];
    const float* wr = w_h2e + (size_t)tid * H_;
#pragma unroll 8
    for (int k = 0; k < H_; k++) acc += sp[k] * wr[k];
    g_ae[b * E_ + tid] = acc;
}

// ---------------- entry point -----------------------------------------------
extern "C" void kernel_launch(void* const* d_in, const int* in_sizes, int n_in,
                              void* d_out, int out_size) {
    const int*   x       = (const int*)d_in[0];
    const int*   lengths = (const int*)d_in[1];
    const float* emb     = (const float*)d_in[2];
    const float* w_ih    = (const float*)d_in[3];
    const float* w_hh    = (const float*)d_in[4];
    const float* b_ih    = (const float*)d_in[5];
    const float* b_hh    = (const float*)d_in[6];
    const float* wq      = (const float*)d_in[7];
    const float* bq      = (const float*)d_in[8];
    const float* wk      = (const float*)d_in[9];
    const float* bk      = (const float*)d_in[10];
    const float* wv      = (const float*)d_in[11];
    const float* bv      = (const float*)d_in[12];
    const float* wo      = (const float*)d_in[13];
    const float* bo      = (const float*)d_in[14];
    const float* w_h2e   = (const float*)d_in[15];
    const float* b_h2e   = (const float*)d_in[16];
    float* out = (float*)d_out;

    float *p_embs, *p_bsum, *p_Xg, *p_lo, *p_Q, *p_K, *p_V, *p_w, *p_mho, *p_ae;
    cudaGetSymbolAddress((void**)&p_embs, g_embs);
    cudaGetSymbolAddress((void**)&p_bsum, g_bsum);
    cudaGetSymbolAddress((void**)&p_Xg,   g_Xg);
    cudaGetSymbolAddress((void**)&p_lo,   g_lstm_out);
    cudaGetSymbolAddress((void**)&p_Q,    g_Q);
    cudaGetSymbolAddress((void**)&p_K,    g_K);
    cudaGetSymbolAddress((void**)&p_V,    g_V);
    cudaGetSymbolAddress((void**)&p_w,    g_wout);
    cudaGetSymbolAddress((void**)&p_mho,  g_mho);
    cudaGetSymbolAddress((void**)&p_ae,   g_ae);

    static bool attr_set = false;
    if (!attr_set) {
        cudaFuncSetAttribute(lstm_persistent,
                             cudaFuncAttributeMaxDynamicSharedMemorySize,
                             LSTM_SMEM_BYTES);
        attr_set = true;
    }

    zero_init_kernel<<<(B_ * H_ + 255) / 256, 256>>>();
    bias_sum_kernel<<<(G4_ + 255) / 256, 256>>>(b_ih, b_hh);
    gather_square_kernel<<<(TB_ * E_ / 4 + 255) / 256, 256>>>(x, emb);

    // Xg = embs @ w_ih^T + (b_ih + b_hh)
    gemm_tf32<false><<<dim3(G4_ / 128, TB_ / 128), 256>>>(p_embs, w_ih, p_bsum, p_Xg, TB_, G4_, E_);

    // LSTM recurrence: ONE persistent kernel, 64 steps, global barrier
    lstm_persistent<<<128, 256, LSTM_SMEM_BYTES>>>(p_Xg, w_hh, lengths);

    // QKV projections
    gemm_tf32<false><<<dim3(H_ / 128, TB_ / 128), 256>>>(p_lo, wq, bq, p_Q, TB_, H_, H_);
    gemm_tf32<false><<<dim3(H_ / 128, TB_ / 128), 256>>>(p_lo, wk, bk, p_K, TB_, H_, H_);
    gemm_tf32<false><<<dim3(H_ / 128, TB_ / 128), 256>>>(p_lo, wv, bv, p_V, TB_, H_, H_);

    attention_kernel<<<dim3(B_, NH_), 256>>>(p_Q, p_K, p_V, lengths, p_w);

    // output projection
    gemm_tf32<false><<<dim3(H_ / 128, TB_ / 128), 256>>>(p_w, wo, bo, p_mho, TB_, H_, H_);

    // fused mean-pool + hidden_to_embedding
    pool_h2e_kernel<<<B_, 128>>>(w_h2e, b_h2e);

    // final scores = ae @ emb^T
    gemm_tf32<true><<<dim3((NITEMS + 127) / 128, B_ / 128), 256>>>(p_ae, emb, nullptr, out, B_, NITEMS, E_);
}

// round 7
// speedup vs baseline: 2.9459x; 1.3472x over previous
#include <cuda_runtime.h>
#include <math.h>
#include <stdint.h>

// Problem constants
constexpr int T_ = 64;
constexpr int B_ = 256;
constexpr int NITEMS = 100000;
constexpr int E_ = 128;
constexpr int H_ = 512;
constexpr int NH_ = 8;
constexpr int G4_ = 4 * H_;   // 2048
constexpr int TB_ = T_ * B_;  // 16384

// ---------------- scratch (device globals) ----------------------------------
__device__ float g_embs[TB_ * E_];
__device__ float g_bsum[G4_];
__device__ float g_hseq[(T_ + 1) * B_ * H_];   // h per step (fresh buffer/step)
__device__ float g_lstm_out[TB_ * H_];         // (B,T,H)
__device__ float g_QKV[TB_ * 3 * H_];          // [TB][1536]: Q|K|V
__device__ float g_wout[TB_ * H_];
__device__ float g_mho[TB_ * H_];
__device__ float g_ae[B_ * E_];
__device__ unsigned int g_bar4[64];            // 4 groups, padded

// ---------------- helpers ----------------------------------------------------
__device__ __forceinline__ float tf32r(float x) {
    uint32_t u;
    asm("cvt.rna.tf32.f32 %0, %1;" : "=r"(u) : "f"(x));
    return __uint_as_float(u);
}

__device__ __forceinline__ void mma_tf32(float c[4],
                                         float a0, float a1, float a2, float a3,
                                         float b0, float b1) {
    asm volatile(
        "mma.sync.aligned.m16n8k8.row.col.f32.tf32.tf32.f32 "
        "{%0,%1,%2,%3},{%4,%5,%6,%7},{%8,%9},{%0,%1,%2,%3};"
        : "+f"(c[0]), "+f"(c[1]), "+f"(c[2]), "+f"(c[3])
        : "r"(__float_as_uint(a0)), "r"(__float_as_uint(a1)),
          "r"(__float_as_uint(a2)), "r"(__float_as_uint(a3)),
          "r"(__float_as_uint(b0)), "r"(__float_as_uint(b1)));
}

__device__ __forceinline__ float sigmoidf_(float x) {
    return 1.f / (1.f + expf(-x));
}

// ---------------- small kernels ---------------------------------------------
__global__ void zero_init_kernel() {
    int i = blockIdx.x * blockDim.x + threadIdx.x;
    if (i < B_ * H_) g_hseq[i] = 0.f;
    if (i < 64) g_bar4[i] = 0u;
}

__global__ void bias_sum_kernel(const float* __restrict__ b_ih,
                                const float* __restrict__ b_hh) {
    int i = blockIdx.x * blockDim.x + threadIdx.x;
    if (i < G4_) g_bsum[i] = b_ih[i] + b_hh[i];
}

__global__ void gather_square_kernel(const int* __restrict__ x,
                                     const float* __restrict__ emb) {
    int fi = blockIdx.x * blockDim.x + threadIdx.x;
    int row = fi >> 5;
    int c4  = fi & 31;
    int id = x[row];
    float4 v = ((const float4*)(emb + (size_t)id * E_))[c4];
    float4 o;
    o.x = v.x * v.x; o.y = v.y * v.y; o.z = v.z * v.z; o.w = v.w * v.w;
    ((float4*)g_embs)[fi] = o;
}

// ---------------- tf32 tensor-core GEMM: C = A(MxK) W(NxK)^T + bias ----------
template<bool CHECKN>
__global__ __launch_bounds__(256, 2)
void gemm_tf32(const float* __restrict__ A, const float* __restrict__ W,
               const float* __restrict__ bias, float* __restrict__ C,
               int M, int N, int K) {
    __shared__ __align__(16) float As[2][128][20];
    __shared__ __align__(16) float Bs[2][128][20];

    const int tid = threadIdx.x;
    const int lane = tid & 31;
    const int wid = tid >> 5;
    const int wm = (wid & 3) * 32;
    const int wn = (wid >> 2) * 64;
    const int bm = blockIdx.y * 128;
    const int bn = blockIdx.x * 128;
    const int lr = tid >> 1;
    const int lk = (tid & 1) * 8;

    int wrow = bn + lr;
    bool wok = true;
    if (CHECKN) { wok = (wrow < N); if (!wok) wrow = N - 1; }
    const float* Ap = A + (size_t)(bm + lr) * K + lk;
    const float* Wp = W + (size_t)wrow * K + lk;

    float acc[2][8][4];
#pragma unroll
    for (int mt = 0; mt < 2; mt++)
#pragma unroll
        for (int nt = 0; nt < 8; nt++)
#pragma unroll
            for (int q = 0; q < 4; q++) acc[mt][nt][q] = 0.f;

    const int gq = lane >> 2;
    const int tg = lane & 3;

    float4 pa0, pa1, pb0, pb1;
    pa0 = *(const float4*)(Ap);
    pa1 = *(const float4*)(Ap + 4);
    if (!CHECKN || wok) {
        pb0 = *(const float4*)(Wp);
        pb1 = *(const float4*)(Wp + 4);
    } else { pb0 = make_float4(0,0,0,0); pb1 = pb0; }

#define GEMM_STAGE(BUF)                                                       \
    {                                                                         \
        float4 ca0 = make_float4(tf32r(pa0.x), tf32r(pa0.y), tf32r(pa0.z), tf32r(pa0.w)); \
        float4 ca1 = make_float4(tf32r(pa1.x), tf32r(pa1.y), tf32r(pa1.z), tf32r(pa1.w)); \
        float4 cb0 = make_float4(tf32r(pb0.x), tf32r(pb0.y), tf32r(pb0.z), tf32r(pb0.w)); \
        float4 cb1 = make_float4(tf32r(pb1.x), tf32r(pb1.y), tf32r(pb1.z), tf32r(pb1.w)); \
        *(float4*)&As[BUF][lr][lk]     = ca0;                                 \
        *(float4*)&As[BUF][lr][lk + 4] = ca1;                                 \
        *(float4*)&Bs[BUF][lr][lk]     = cb0;                                 \
        *(float4*)&Bs[BUF][lr][lk + 4] = cb1;                                 \
    }

#define GEMM_COMPUTE(BUF)                                                     \
    _Pragma("unroll")                                                         \
    for (int ks = 0; ks < 16; ks += 8) {                                      \
        float a[2][4];                                                        \
        float b[8][2];                                                        \
        _Pragma("unroll")                                                     \
        for (int mt = 0; mt < 2; mt++) {                                      \
            int r = wm + mt * 16 + gq;                                        \
            int c = ks + tg;                                                  \
            a[mt][0] = As[BUF][r][c];                                         \
            a[mt][1] = As[BUF][r + 8][c];                                     \
            a[mt][2] = As[BUF][r][c + 4];                                     \
            a[mt][3] = As[BUF][r + 8][c + 4];                                 \
        }                                                                     \
        _Pragma("unroll")                                                     \
        for (int nt = 0; nt < 8; nt++) {                                      \
            int n = wn + nt * 8 + gq;                                         \
            b[nt][0] = Bs[BUF][n][ks + tg];                                   \
            b[nt][1] = Bs[BUF][n][ks + tg + 4];                               \
        }                                                                     \
        _Pragma("unroll")                                                     \
        for (int mt = 0; mt < 2; mt++)                                        \
            _Pragma("unroll")                                                 \
            for (int nt = 0; nt < 8; nt++)                                    \
                mma_tf32(acc[mt][nt], a[mt][0], a[mt][1], a[mt][2], a[mt][3], \
                         b[nt][0], b[nt][1]);                                 \
    }

    GEMM_STAGE(0)
    __syncthreads();

    int buf = 0;
    for (int k0 = 16; k0 < K; k0 += 16) {
        pa0 = *(const float4*)(Ap + k0);
        pa1 = *(const float4*)(Ap + k0 + 4);
        if (!CHECKN || wok) {
            pb0 = *(const float4*)(Wp + k0);
            pb1 = *(const float4*)(Wp + k0 + 4);
        } else { pb0 = make_float4(0,0,0,0); pb1 = pb0; }
        if (buf == 0) { GEMM_COMPUTE(0) GEMM_STAGE(1) }
        else          { GEMM_COMPUTE(1) GEMM_STAGE(0) }
        __syncthreads();
        buf ^= 1;
    }
    if (buf == 0) { GEMM_COMPUTE(0) } else { GEMM_COMPUTE(1) }

#pragma unroll
    for (int mt = 0; mt < 2; mt++) {
        int r = bm + wm + mt * 16 + gq;
#pragma unroll
        for (int nt = 0; nt < 8; nt++) {
            int cgl = bn + wn + nt * 8 + 2 * tg;
            if (CHECKN && cgl >= N) continue;
            float bv0 = 0.f, bv1 = 0.f;
            if (bias) { bv0 = bias[cgl]; bv1 = bias[cgl + 1]; }
            *(float2*)&C[(size_t)r * N + cgl] =
                make_float2(acc[mt][nt][0] + bv0, acc[mt][nt][1] + bv1);
            *(float2*)&C[(size_t)(r + 8) * N + cgl] =
                make_float2(acc[mt][nt][2] + bv0, acc[mt][nt][3] + bv1);
        }
    }
#undef GEMM_STAGE
#undef GEMM_COMPUTE
}

// ---------------- fused QKV GEMM: C[TB][1536] = A @ [wq|wk|wv]^T + bias ------
__global__ __launch_bounds__(256, 2)
void gemm_qkv(const float* __restrict__ A,
              const float* __restrict__ wq, const float* __restrict__ wk,
              const float* __restrict__ wv,
              const float* __restrict__ bq, const float* __restrict__ bk,
              const float* __restrict__ bv,
              float* __restrict__ C) {
    __shared__ __align__(16) float As[2][128][20];
    __shared__ __align__(16) float Bs[2][128][20];
    constexpr int K = H_, N = 3 * H_;

    const int tid = threadIdx.x;
    const int lane = tid & 31;
    const int wid = tid >> 5;
    const int wm = (wid & 3) * 32;
    const int wn = (wid >> 2) * 64;
    const int bm = blockIdx.y * 128;
    const int bn = blockIdx.x * 128;
    const int lr = tid >> 1;
    const int lk = (tid & 1) * 8;

    const int wrow = bn + lr;
    const int sel = wrow >> 9;
    const int wl = wrow & 511;
    const float* Wbase = (sel == 0) ? wq : ((sel == 1) ? wk : wv);
    const float* Ap = A + (size_t)(bm + lr) * K + lk;
    const float* Wp = Wbase + (size_t)wl * K + lk;

    float acc[2][8][4];
#pragma unroll
    for (int mt = 0; mt < 2; mt++)
#pragma unroll
        for (int nt = 0; nt < 8; nt++)
#pragma unroll
            for (int q = 0; q < 4; q++) acc[mt][nt][q] = 0.f;

    const int gq = lane >> 2;
    const int tg = lane & 3;

    float4 pa0, pa1, pb0, pb1;
    pa0 = *(const float4*)(Ap);
    pa1 = *(const float4*)(Ap + 4);
    pb0 = *(const float4*)(Wp);
    pb1 = *(const float4*)(Wp + 4);

#define QKV_STAGE(BUF)                                                        \
    {                                                                         \
        float4 ca0 = make_float4(tf32r(pa0.x), tf32r(pa0.y), tf32r(pa0.z), tf32r(pa0.w)); \
        float4 ca1 = make_float4(tf32r(pa1.x), tf32r(pa1.y), tf32r(pa1.z), tf32r(pa1.w)); \
        float4 cb0 = make_float4(tf32r(pb0.x), tf32r(pb0.y), tf32r(pb0.z), tf32r(pb0.w)); \
        float4 cb1 = make_float4(tf32r(pb1.x), tf32r(pb1.y), tf32r(pb1.z), tf32r(pb1.w)); \
        *(float4*)&As[BUF][lr][lk]     = ca0;                                 \
        *(float4*)&As[BUF][lr][lk + 4] = ca1;                                 \
        *(float4*)&Bs[BUF][lr][lk]     = cb0;                                 \
        *(float4*)&Bs[BUF][lr][lk + 4] = cb1;                                 \
    }

#define QKV_COMPUTE(BUF)                                                      \
    _Pragma("unroll")                                                         \
    for (int ks = 0; ks < 16; ks += 8) {                                      \
        float a[2][4];                                                        \
        float b[8][2];                                                        \
        _Pragma("unroll")                                                     \
        for (int mt = 0; mt < 2; mt++) {                                      \
            int r = wm + mt * 16 + gq;                                        \
            int c = ks + tg;                                                  \
            a[mt][0] = As[BUF][r][c];                                         \
            a[mt][1] = As[BUF][r + 8][c];                                     \
            a[mt][2] = As[BUF][r][c + 4];                                     \
            a[mt][3] = As[BUF][r + 8][c + 4];                                 \
        }                                                                     \
        _Pragma("unroll")                                                     \
        for (int nt = 0; nt < 8; nt++) {                                      \
            int n = wn + nt * 8 + gq;                                         \
            b[nt][0] = Bs[BUF][n][ks + tg];                                   \
            b[nt][1] = Bs[BUF][n][ks + tg + 4];                               \
        }                                                                     \
        _Pragma("unroll")                                                     \
        for (int mt = 0; mt < 2; mt++)                                        \
            _Pragma("unroll")                                                 \
            for (int nt = 0; nt < 8; nt++)                                    \
                mma_tf32(acc[mt][nt], a[mt][0], a[mt][1], a[mt][2], a[mt][3], \
                         b[nt][0], b[nt][1]);                                 \
    }

    QKV_STAGE(0)
    __syncthreads();

    int buf = 0;
    for (int k0 = 16; k0 < K; k0 += 16) {
        pa0 = *(const float4*)(Ap + k0);
        pa1 = *(const float4*)(Ap + k0 + 4);
        pb0 = *(const float4*)(Wp + k0);
        pb1 = *(const float4*)(Wp + k0 + 4);
        if (buf == 0) { QKV_COMPUTE(0) QKV_STAGE(1) }
        else          { QKV_COMPUTE(1) QKV_STAGE(0) }
        __syncthreads();
        buf ^= 1;
    }
    if (buf == 0) { QKV_COMPUTE(0) } else { QKV_COMPUTE(1) }

#pragma unroll
    for (int mt = 0; mt < 2; mt++) {
        int r = bm + wm + mt * 16 + gq;
#pragma unroll
        for (int nt = 0; nt < 8; nt++) {
            int cgl = bn + wn + nt * 8 + 2 * tg;
            int selc = cgl >> 9;
            int lc = cgl & 511;
            const float* bb = (selc == 0) ? bq : ((selc == 1) ? bk : bv);
            float bv0 = bb[lc], bv1 = bb[lc + 1];
            *(float2*)&C[(size_t)r * N + cgl] =
                make_float2(acc[mt][nt][0] + bv0, acc[mt][nt][1] + bv1);
            *(float2*)&C[(size_t)(r + 8) * N + cgl] =
                make_float2(acc[mt][nt][2] + bv0, acc[mt][nt][3] + bv1);
        }
    }
#undef QKV_STAGE
#undef QKV_COMPUTE
}

// ---------------- persistent tensor-core LSTM (input GEMM folded in) --------
// 128 resident blocks (32 j-strips x 4 b-groups), 256 threads.
// smem: w_hh slice [64][516], w_ih slice [64][132], h/e staging [2][64][68],
// preacts [64][68]. Total 213 KB.
constexpr int WHH_STR = 516;
constexpr int WIH_STR = 132;
constexpr int HS_STR  = 68;
constexpr int WHH_FLOATS = 64 * WHH_STR;
constexpr int WIH_FLOATS = 64 * WIH_STR;
constexpr int HS_FLOATS  = 64 * HS_STR;
constexpr int LSTM_SMEM_BYTES =
    (WHH_FLOATS + WIH_FLOATS + 2 * HS_FLOATS + 64 * 68) * 4;

__device__ __forceinline__ void lstm_comp(const float* HS, const float* WS,
                                          int wstr, int coff,
                                          int wm, int wn, int gq, int tg,
                                          float (&acc)[2][2][4]) {
#pragma unroll
    for (int ks = 0; ks < 64; ks += 8) {
        float a[2][4];
        float bf[2][2];
#pragma unroll
        for (int mt = 0; mt < 2; mt++) {
            int r = wm + mt * 16 + gq;
            int cc = ks + tg;
            a[mt][0] = HS[r * HS_STR + cc];
            a[mt][1] = HS[(r + 8) * HS_STR + cc];
            a[mt][2] = HS[r * HS_STR + cc + 4];
            a[mt][3] = HS[(r + 8) * HS_STR + cc + 4];
        }
#pragma unroll
        for (int nt = 0; nt < 2; nt++) {
            int n = wn + nt * 8 + gq;
            bf[nt][0] = WS[n * wstr + coff + ks + tg];
            bf[nt][1] = WS[n * wstr + coff + ks + tg + 4];
        }
#pragma unroll
        for (int mt = 0; mt < 2; mt++)
#pragma unroll
            for (int nt = 0; nt < 2; nt++)
                mma_tf32(acc[mt][nt], a[mt][0], a[mt][1], a[mt][2], a[mt][3],
                         bf[nt][0], bf[nt][1]);
    }
}

__device__ __forceinline__ void lstm_stage(float* HS, int row, int cg,
                                           float4 q0, float4 q1,
                                           float4 q2, float4 q3) {
    float* d = HS + row * HS_STR + cg * 16;
    d[0]  = tf32r(q0.x); d[1]  = tf32r(q0.y); d[2]  = tf32r(q0.z); d[3]  = tf32r(q0.w);
    d[4]  = tf32r(q1.x); d[5]  = tf32r(q1.y); d[6]  = tf32r(q1.z); d[7]  = tf32r(q1.w);
    d[8]  = tf32r(q2.x); d[9]  = tf32r(q2.y); d[10] = tf32r(q2.z); d[11] = tf32r(q2.w);
    d[12] = tf32r(q3.x); d[13] = tf32r(q3.y); d[14] = tf32r(q3.z); d[15] = tf32r(q3.w);
}

__global__ __launch_bounds__(256, 1)
void lstm_persistent(const float* __restrict__ w_ih,    // (4H,E)
                     const float* __restrict__ w_hh,    // (4H,H)
                     const int* __restrict__ lengths) {
    extern __shared__ __align__(16) float dsm[];
    float* ws_hh = dsm;
    float* ws_ih = ws_hh + WHH_FLOATS;
    float* hsA   = ws_ih + WIH_FLOATS;
    float* hsB   = hsA + HS_FLOATS;
    float* ps    = hsB + HS_FLOATS;

    const int tid = threadIdx.x;
    const int lane = tid & 31;
    const int wid = tid >> 5;
    const int wm = (wid & 1) * 32;
    const int wn = (wid >> 1) * 16;
    const int j0 = (blockIdx.x & 31) * 16;
    const int b0 = (blockIdx.x >> 5) * 64;
    const int grp = blockIdx.x >> 5;

    const int gq = lane >> 2;
    const int tg = lane & 3;

    // load w_hh slice (rows n: gate = n>>4, jl = n&15)
    for (int idx = tid; idx < 64 * 128; idx += 256) {
        int n = idx >> 7;
        int k4 = (idx & 127) * 4;
        int g = n >> 4, jl = n & 15;
        float4 v = *(const float4*)(w_hh + (size_t)(g * H_ + j0 + jl) * H_ + k4);
        float* dst = ws_hh + n * WHH_STR + k4;
        dst[0] = tf32r(v.x); dst[1] = tf32r(v.y);
        dst[2] = tf32r(v.z); dst[3] = tf32r(v.w);
    }
    // load w_ih slice
    for (int idx = tid; idx < 64 * 32; idx += 256) {
        int n = idx >> 5;
        int k4 = (idx & 31) * 4;
        int g = n >> 4, jl = n & 15;
        float4 v = *(const float4*)(w_ih + (size_t)(g * H_ + j0 + jl) * E_ + k4);
        float* dst = ws_ih + n * WIH_STR + k4;
        dst[0] = tf32r(v.x); dst[1] = tf32r(v.y);
        dst[2] = tf32r(v.z); dst[3] = tf32r(v.w);
    }
    __syncthreads();

    // staging indices: row 0..63, cg 0..3 (16 cols each)
    const int row = tid >> 2;
    const int cg = tid & 3;

    // epilogue cell mapping: idx = tid + p*256 -> jloc = idx&15, bl = idx>>4
    int lenp[4];
    float bi[4], bfo[4], bg[4], bo4[4];
    float creg[4];
#pragma unroll
    for (int p = 0; p < 4; p++) {
        int idx = tid + p * 256;
        int jloc = idx & 15;
        int bl = idx >> 4;        // 0..63
        lenp[p] = lengths[b0 + bl];
        int j = j0 + jloc;
        bi[p]  = g_bsum[j];
        bfo[p] = g_bsum[H_ + j];
        bg[p]  = g_bsum[2 * H_ + j];
        bo4[p] = g_bsum[3 * H_ + j];
        creg[p] = 0.f;
    }

    for (int t = 0; t < T_; t++) {
        const float* eb = g_embs + ((size_t)t * B_ + b0 + row) * E_ + cg * 16;
        const float* hb = g_hseq + (size_t)t * B_ * H_ + (size_t)(b0 + row) * H_ + cg * 16;

        float acc[2][2][4];
#pragma unroll
        for (int mt = 0; mt < 2; mt++)
#pragma unroll
            for (int nt = 0; nt < 2; nt++)
#pragma unroll
                for (int q = 0; q < 4; q++) acc[mt][nt][q] = 0.f;

        float4 q0, q1, q2, q3;
        // E chunk 0
        q0 = *(const float4*)(eb);      q1 = *(const float4*)(eb + 4);
        q2 = *(const float4*)(eb + 8);  q3 = *(const float4*)(eb + 12);
        lstm_stage(hsA, row, cg, q0, q1, q2, q3);
        __syncthreads();
        // E chunk 1 fetch; compute E0
        q0 = *(const float4*)(eb + 64);      q1 = *(const float4*)(eb + 68);
        q2 = *(const float4*)(eb + 72);      q3 = *(const float4*)(eb + 76);
        lstm_comp(hsA, ws_ih, WIH_STR, 0, wm, wn, gq, tg, acc);
        lstm_stage(hsB, row, cg, q0, q1, q2, q3);
        __syncthreads();
        // H chunk 0 fetch; compute E1
        q0 = *(const float4*)(hb);      q1 = *(const float4*)(hb + 4);
        q2 = *(const float4*)(hb + 8);  q3 = *(const float4*)(hb + 12);
        lstm_comp(hsB, ws_ih, WIH_STR, 64, wm, wn, gq, tg, acc);
        lstm_stage(hsA, row, cg, q0, q1, q2, q3);
        __syncthreads();
        // H chunks 1..7
        for (int ch = 1; ch < 8; ch++) {
            const float* s = hb + ch * 64;
            q0 = *(const float4*)(s);      q1 = *(const float4*)(s + 4);
            q2 = *(const float4*)(s + 8);  q3 = *(const float4*)(s + 12);
            if (ch & 1) {
                lstm_comp(hsA, ws_hh, WHH_STR, (ch - 1) * 64, wm, wn, gq, tg, acc);
                lstm_stage(hsB, row, cg, q0, q1, q2, q3);
            } else {
                lstm_comp(hsB, ws_hh, WHH_STR, (ch - 1) * 64, wm, wn, gq, tg, acc);
                lstm_stage(hsA, row, cg, q0, q1, q2, q3);
            }
            __syncthreads();
        }
        lstm_comp(hsB, ws_hh, WHH_STR, 7 * 64, wm, wn, gq, tg, acc);

        // preacts -> shared
#pragma unroll
        for (int mt = 0; mt < 2; mt++) {
            int r = wm + mt * 16 + gq;
#pragma unroll
            for (int nt = 0; nt < 2; nt++) {
                int c = wn + nt * 8 + 2 * tg;
                *(float2*)&ps[r * 68 + c] = make_float2(acc[mt][nt][0], acc[mt][nt][1]);
                *(float2*)&ps[(r + 8) * 68 + c] = make_float2(acc[mt][nt][2], acc[mt][nt][3]);
            }
        }
        __syncthreads();

        // gate epilogue
        float* hout = g_hseq + (size_t)(t + 1) * B_ * H_;
#pragma unroll
        for (int p = 0; p < 4; p++) {
            int idx = tid + p * 256;
            int jloc = idx & 15;
            int bl = idx >> 4;
            int b = b0 + bl;
            int j = j0 + jloc;
            float gi = sigmoidf_(ps[bl * 68 + jloc]      + bi[p]);
            float gf = sigmoidf_(ps[bl * 68 + 16 + jloc] + bfo[p]);
            float gg = tanhf(    ps[bl * 68 + 32 + jloc] + bg[p]);
            float go = sigmoidf_(ps[bl * 68 + 48 + jloc] + bo4[p]);
            float cn = gf * creg[p] + gi * gg;
            creg[p] = cn;
            float hn = go * tanhf(cn);
            hout[(size_t)b * H_ + j] = hn;
            g_lstm_out[(size_t)(b * T_ + t) * H_ + j] = (t < lenp[p]) ? hn : 0.f;
        }
        __syncthreads();

        // group barrier (32 blocks sharing b0)
        if (t != T_ - 1) {
            if (tid == 0) {
                __threadfence();
                atomicAdd(&g_bar4[grp * 16], 1u);
                unsigned target = 32u * (unsigned)(t + 1);
                volatile unsigned* vb = &g_bar4[grp * 16];
                while (*vb < target) __nanosleep(32);
            }
            __syncthreads();
        }
    }
}

// ---------------- attention: one block per (b, head), QKV packed ------------
__global__ __launch_bounds__(256)
void attention_kernel(const float* __restrict__ QKV,
                      const int* __restrict__ lengths,
                      float* __restrict__ Wout) {
    __shared__ float qs[64 * 64];
    __shared__ float ks[64 * 64];
    __shared__ float ss[64 * 64];
    const int b = blockIdx.x, nh = blockIdx.y;
    const int tid = threadIdx.x;
    const int len = lengths[b];
    const size_t qkvbase = ((size_t)b * 64) * 1536 + nh * 64;
    const size_t obase = ((size_t)b * 64) * 512 + nh * 64;

#pragma unroll
    for (int l = 0; l < 4; l++) {
        int fidx = tid + (l << 8);
        int r = fidx & 63, c4 = fidx >> 6;
        float4 qv = *(const float4*)(QKV + qkvbase + (size_t)r * 1536 + c4 * 4);
        float4 kv = *(const float4*)(QKV + qkvbase + 512 + (size_t)r * 1536 + c4 * 4);
        qs[(c4 * 4 + 0) * 64 + r] = qv.x; qs[(c4 * 4 + 1) * 64 + r] = qv.y;
        qs[(c4 * 4 + 2) * 64 + r] = qv.z; qs[(c4 * 4 + 3) * 64 + r] = qv.w;
        ks[(c4 * 4 + 0) * 64 + r] = kv.x; ks[(c4 * 4 + 1) * 64 + r] = kv.y;
        ks[(c4 * 4 + 2) * 64 + r] = kv.z; ks[(c4 * 4 + 3) * 64 + r] = kv.w;
    }
    __syncthreads();

    const int tx = tid & 15, ty = tid >> 4;
    const int r0 = ty * 4, c0 = tx * 4;
    float acc[4][4];
#pragma unroll
    for (int i = 0; i < 4; i++)
#pragma unroll
        for (int j = 0; j < 4; j++) acc[i][j] = 0.f;

#pragma unroll 8
    for (int k = 0; k < 64; k++) {
        float4 aq = *(const float4*)&qs[k * 64 + r0];
        float4 bk = *(const float4*)&ks[k * 64 + c0];
        float a[4] = {aq.x, aq.y, aq.z, aq.w};
        float bb[4] = {bk.x, bk.y, bk.z, bk.w};
#pragma unroll
        for (int i = 0; i < 4; i++)
#pragma unroll
            for (int j = 0; j < 4; j++) acc[i][j] += a[i] * bb[j];
    }
#pragma unroll
    for (int i = 0; i < 4; i++)
#pragma unroll
        for (int j = 0; j < 4; j++) {
            int c = c0 + j;
            ss[(r0 + i) * 64 + c] = (c < len) ? acc[i][j] * 0.125f : -1e30f;
        }
    __syncthreads();

    float* vs = qs;
#pragma unroll
    for (int l = 0; l < 4; l++) {
        int fidx = tid + (l << 8);
        int r = fidx >> 4, c4 = fidx & 15;
        ((float4*)vs)[fidx] =
            *(const float4*)(QKV + qkvbase + 1024 + (size_t)r * 1536 + c4 * 4);
    }
    if (tid < 64) {
        float m = -1e30f;
#pragma unroll 8
        for (int c = 0; c < 64; c++) m = fmaxf(m, ss[tid * 64 + c]);
        float s = 0.f;
#pragma unroll 8
        for (int c = 0; c < 64; c++) {
            float e = expf(ss[tid * 64 + c] - m);
            ss[tid * 64 + c] = e;
            s += e;
        }
        float inv = 1.f / s;
#pragma unroll 8
        for (int c = 0; c < 64; c++) ss[tid * 64 + c] *= inv;
    }
    __syncthreads();

    float o[4][4];
#pragma unroll
    for (int i = 0; i < 4; i++)
#pragma unroll
        for (int j = 0; j < 4; j++) o[i][j] = 0.f;
#pragma unroll 8
    for (int k = 0; k < 64; k++) {
        float a[4];
#pragma unroll
        for (int i = 0; i < 4; i++) a[i] = ss[(r0 + i) * 64 + k];
        float4 vv4 = *(const float4*)&vs[k * 64 + c0];
        float vv[4] = {vv4.x, vv4.y, vv4.z, vv4.w};
#pragma unroll
        for (int i = 0; i < 4; i++)
#pragma unroll
            for (int j = 0; j < 4; j++) o[i][j] += a[i] * vv[j];
    }
#pragma unroll
    for (int i = 0; i < 4; i++) {
        float4 ov = make_float4(o[i][0], o[i][1], o[i][2], o[i][3]);
        *(float4*)(Wout + obase + (size_t)(r0 + i) * 512 + c0) = ov;
    }
}

// ---------------- fused meanpool + hidden_to_embedding ----------------------
__global__ __launch_bounds__(128)
void pool_h2e_kernel(const float* __restrict__ w_h2e,
                     const float* __restrict__ b_h2e) {
    __shared__ float sp[H_];
    const int b = blockIdx.x;
    const int tid = threadIdx.x;
    float s0 = 0.f, s1 = 0.f, s2 = 0.f, s3 = 0.f;
    const float* src = g_mho + (size_t)b * 64 * H_ + tid * 4;
#pragma unroll 8
    for (int t = 0; t < 64; t++) {
        float4 v = *(const float4*)(src + (size_t)t * H_);
        s0 += v.x; s1 += v.y; s2 += v.z; s3 += v.w;
    }
    sp[tid * 4 + 0] = s0 * (1.f / 64.f);
    sp[tid * 4 + 1] = s1 * (1.f / 64.f);
    sp[tid * 4 + 2] = s2 * (1.f / 64.f);
    sp[tid * 4 + 3] = s3 * (1.f / 64.f);
    __syncthreads();
    float acc = b_h2e[tid];
    const float* wr = w_h2e + (size_t)tid * H_;
#pragma unroll 8
    for (int k = 0; k < H_; k++) acc += sp[k] * wr[k];
    g_ae[b * E_ + tid] = acc;
}

// ---------------- entry point -----------------------------------------------
extern "C" void kernel_launch(void* const* d_in, const int* in_sizes, int n_in,
                              void* d_out, int out_size) {
    const int*   x       = (const int*)d_in[0];
    const int*   lengths = (const int*)d_in[1];
    const float* emb     = (const float*)d_in[2];
    const float* w_ih    = (const float*)d_in[3];
    const float* w_hh    = (const float*)d_in[4];
    const float* b_ih    = (const float*)d_in[5];
    const float* b_hh    = (const float*)d_in[6];
    const float* wq      = (const float*)d_in[7];
    const float* bq      = (const float*)d_in[8];
    const float* wk      = (const float*)d_in[9];
    const float* bk      = (const float*)d_in[10];
    const float* wv      = (const float*)d_in[11];
    const float* bv      = (const float*)d_in[12];
    const float* wo      = (const float*)d_in[13];
    const float* bo      = (const float*)d_in[14];
    const float* w_h2e   = (const float*)d_in[15];
    const float* b_h2e   = (const float*)d_in[16];
    float* out = (float*)d_out;

    float *p_lo, *p_qkv, *p_w, *p_mho, *p_ae;
    cudaGetSymbolAddress((void**)&p_lo,   g_lstm_out);
    cudaGetSymbolAddress((void**)&p_qkv,  g_QKV);
    cudaGetSymbolAddress((void**)&p_w,    g_wout);
    cudaGetSymbolAddress((void**)&p_mho,  g_mho);
    cudaGetSymbolAddress((void**)&p_ae,   g_ae);

    static bool attr_set = false;
    if (!attr_set) {
        cudaFuncSetAttribute(lstm_persistent,
                             cudaFuncAttributeMaxDynamicSharedMemorySize,
                             LSTM_SMEM_BYTES);
        attr_set = true;
    }

    zero_init_kernel<<<(B_ * H_ + 255) / 256, 256>>>();
    bias_sum_kernel<<<(G4_ + 255) / 256, 256>>>(b_ih, b_hh);
    gather_square_kernel<<<(TB_ * E_ / 4 + 255) / 256, 256>>>(x, emb);

    // LSTM recurrence with folded input GEMM: one persistent kernel
    lstm_persistent<<<128, 256, LSTM_SMEM_BYTES>>>(w_ih, w_hh, lengths);

    // fused QKV projection -> [TB][1536]
    gemm_qkv<<<dim3(12, TB_ / 128), 256>>>(p_lo, wq, wk, wv, bq, bk, bv, p_qkv);

    attention_kernel<<<dim3(B_, NH_), 256>>>(p_qkv, lengths, p_w);

    // output projection
    gemm_tf32<false><<<dim3(H_ / 128, TB_ / 128), 256>>>(p_w, wo, bo, p_mho, TB_, H_, H_);

    // fused mean-pool + hidden_to_embedding
    pool_h2e_kernel<<<B_, 128>>>(w_h2e, b_h2e);

    // final scores = ae @ emb^T
    gemm_tf32<true><<<dim3((NITEMS + 127) / 128, B_ / 128), 256>>>(p_ae, emb, nullptr, out, B_, NITEMS, E_);
}

// round 9
// speedup vs baseline: 3.2205x; 1.0932x over previous
#include <cuda_runtime.h>
#include <math.h>
#include <stdint.h>

// Problem constants
constexpr int T_ = 64;
constexpr int B_ = 256;
constexpr int NITEMS = 100000;
constexpr int E_ = 128;
constexpr int H_ = 512;
constexpr int NH_ = 8;
constexpr int G4_ = 4 * H_;   // 2048
constexpr int TB_ = T_ * B_;  // 16384

// ---------------- scratch (device globals) ----------------------------------
__device__ float g_embs[TB_ * E_];             // tf32-rounded emb[x]^2
__device__ float g_bsum[G4_];
__device__ float g_hseq[(T_ + 1) * B_ * H_];   // tf32-rounded h per step
__device__ float g_lstm_out[TB_ * H_];         // (B,T,H), tf32-rounded
__device__ float g_QKV[TB_ * 3 * H_];          // [TB][1536]: Q|K|V
__device__ float g_wout[TB_ * H_];
__device__ float g_mho[TB_ * H_];
__device__ float g_ae[B_ * E_];
__device__ unsigned int g_bar4[64];            // 4 groups, padded

// ---------------- helpers ----------------------------------------------------
__device__ __forceinline__ float tf32r(float x) {
    uint32_t u;
    asm("cvt.rna.tf32.f32 %0, %1;" : "=r"(u) : "f"(x));
    return __uint_as_float(u);
}

__device__ __forceinline__ void mma_tf32(float c[4],
                                         float a0, float a1, float a2, float a3,
                                         float b0, float b1) {
    asm volatile(
        "mma.sync.aligned.m16n8k8.row.col.f32.tf32.tf32.f32 "
        "{%0,%1,%2,%3},{%4,%5,%6,%7},{%8,%9},{%0,%1,%2,%3};"
        : "+f"(c[0]), "+f"(c[1]), "+f"(c[2]), "+f"(c[3])
        : "r"(__float_as_uint(a0)), "r"(__float_as_uint(a1)),
          "r"(__float_as_uint(a2)), "r"(__float_as_uint(a3)),
          "r"(__float_as_uint(b0)), "r"(__float_as_uint(b1)));
}

__device__ __forceinline__ float sigmoidf_(float x) {
    return 1.f / (1.f + expf(-x));
}

__device__ __forceinline__ void cp16(uint32_t d, const float* s) {
    asm volatile("cp.async.cg.shared.global [%0], [%1], 16;" :: "r"(d), "l"(s));
}
__device__ __forceinline__ void cp_commit() {
    asm volatile("cp.async.commit_group;");
}
template<int N>
__device__ __forceinline__ void cp_wait() {
    asm volatile("cp.async.wait_group %0;" :: "n"(N));
}

// ---------------- small kernels ---------------------------------------------
__global__ void zero_init_kernel() {
    int i = blockIdx.x * blockDim.x + threadIdx.x;
    if (i < B_ * H_) g_hseq[i] = 0.f;
    if (i < 64) g_bar4[i] = 0u;
}

__global__ void bias_sum_kernel(const float* __restrict__ b_ih,
                                const float* __restrict__ b_hh) {
    int i = blockIdx.x * blockDim.x + threadIdx.x;
    if (i < G4_) g_bsum[i] = b_ih[i] + b_hh[i];
}

// embs = tf32r(emb[x]^2) — pre-rounded so the LSTM can cp.async it directly.
__global__ void gather_square_kernel(const int* __restrict__ x,
                                     const float* __restrict__ emb) {
    int fi = blockIdx.x * blockDim.x + threadIdx.x;
    int row = fi >> 5;
    int c4  = fi & 31;
    int id = x[row];
    float4 v = ((const float4*)(emb + (size_t)id * E_))[c4];
    float4 o;
    o.x = tf32r(v.x * v.x); o.y = tf32r(v.y * v.y);
    o.z = tf32r(v.z * v.z); o.w = tf32r(v.w * v.w);
    ((float4*)g_embs)[fi] = o;
}

// ---------------- tf32 tensor-core GEMM: C = A(MxK) W(NxK)^T + bias ----------
template<bool CHECKN>
__global__ __launch_bounds__(256, 2)
void gemm_tf32(const float* __restrict__ A, const float* __restrict__ W,
               const float* __restrict__ bias, float* __restrict__ C,
               int M, int N, int K) {
    __shared__ __align__(16) float As[2][128][20];
    __shared__ __align__(16) float Bs[2][128][20];

    const int tid = threadIdx.x;
    const int lane = tid & 31;
    const int wid = tid >> 5;
    const int wm = (wid & 3) * 32;
    const int wn = (wid >> 2) * 64;
    const int bm = blockIdx.y * 128;
    const int bn = blockIdx.x * 128;
    const int lr = tid >> 1;
    const int lk = (tid & 1) * 8;

    int wrow = bn + lr;
    bool wok = true;
    if (CHECKN) { wok = (wrow < N); if (!wok) wrow = N - 1; }
    const float* Ap = A + (size_t)(bm + lr) * K + lk;
    const float* Wp = W + (size_t)wrow * K + lk;

    float acc[2][8][4];
#pragma unroll
    for (int mt = 0; mt < 2; mt++)
#pragma unroll
        for (int nt = 0; nt < 8; nt++)
#pragma unroll
            for (int q = 0; q < 4; q++) acc[mt][nt][q] = 0.f;

    const int gq = lane >> 2;
    const int tg = lane & 3;

    float4 pa0, pa1, pb0, pb1;
    pa0 = *(const float4*)(Ap);
    pa1 = *(const float4*)(Ap + 4);
    if (!CHECKN || wok) {
        pb0 = *(const float4*)(Wp);
        pb1 = *(const float4*)(Wp + 4);
    } else { pb0 = make_float4(0,0,0,0); pb1 = pb0; }

#define GEMM_STAGE(BUF)                                                       \
    {                                                                         \
        float4 ca0 = make_float4(tf32r(pa0.x), tf32r(pa0.y), tf32r(pa0.z), tf32r(pa0.w)); \
        float4 ca1 = make_float4(tf32r(pa1.x), tf32r(pa1.y), tf32r(pa1.z), tf32r(pa1.w)); \
        float4 cb0 = make_float4(tf32r(pb0.x), tf32r(pb0.y), tf32r(pb0.z), tf32r(pb0.w)); \
        float4 cb1 = make_float4(tf32r(pb1.x), tf32r(pb1.y), tf32r(pb1.z), tf32r(pb1.w)); \
        *(float4*)&As[BUF][lr][lk]     = ca0;                                 \
        *(float4*)&As[BUF][lr][lk + 4] = ca1;                                 \
        *(float4*)&Bs[BUF][lr][lk]     = cb0;                                 \
        *(float4*)&Bs[BUF][lr][lk + 4] = cb1;                                 \
    }

#define GEMM_COMPUTE(BUF)                                                     \
    _Pragma("unroll")                                                         \
    for (int ks = 0; ks < 16; ks += 8) {                                      \
        float a[2][4];                                                        \
        float b[8][2];                                                        \
        _Pragma("unroll")                                                     \
        for (int mt = 0; mt < 2; mt++) {                                      \
            int r = wm + mt * 16 + gq;                                        \
            int c = ks + tg;                                                  \
            a[mt][0] = As[BUF][r][c];                                         \
            a[mt][1] = As[BUF][r + 8][c];                                     \
            a[mt][2] = As[BUF][r][c + 4];                                     \
            a[mt][3] = As[BUF][r + 8][c + 4];                                 \
        }                                                                     \
        _Pragma("unroll")                                                     \
        for (int nt = 0; nt < 8; nt++) {                                      \
            int n = wn + nt * 8 + gq;                                         \
            b[nt][0] = Bs[BUF][n][ks + tg];                                   \
            b[nt][1] = Bs[BUF][n][ks + tg + 4];                               \
        }                                                                     \
        _Pragma("unroll")                                                     \
        for (int mt = 0; mt < 2; mt++)                                        \
            _Pragma("unroll")                                                 \
            for (int nt = 0; nt < 8; nt++)                                    \
                mma_tf32(acc[mt][nt], a[mt][0], a[mt][1], a[mt][2], a[mt][3], \
                         b[nt][0], b[nt][1]);                                 \
    }

    GEMM_STAGE(0)
    __syncthreads();

    int buf = 0;
    for (int k0 = 16; k0 < K; k0 += 16) {
        pa0 = *(const float4*)(Ap + k0);
        pa1 = *(const float4*)(Ap + k0 + 4);
        if (!CHECKN || wok) {
            pb0 = *(const float4*)(Wp + k0);
            pb1 = *(const float4*)(Wp + k0 + 4);
        } else { pb0 = make_float4(0,0,0,0); pb1 = pb0; }
        if (buf == 0) { GEMM_COMPUTE(0) GEMM_STAGE(1) }
        else          { GEMM_COMPUTE(1) GEMM_STAGE(0) }
        __syncthreads();
        buf ^= 1;
    }
    if (buf == 0) { GEMM_COMPUTE(0) } else { GEMM_COMPUTE(1) }

#pragma unroll
    for (int mt = 0; mt < 2; mt++) {
        int r = bm + wm + mt * 16 + gq;
#pragma unroll
        for (int nt = 0; nt < 8; nt++) {
            int cgl = bn + wn + nt * 8 + 2 * tg;
            if (CHECKN && cgl >= N) continue;
            float bv0 = 0.f, bv1 = 0.f;
            if (bias) { bv0 = bias[cgl]; bv1 = bias[cgl + 1]; }
            *(float2*)&C[(size_t)r * N + cgl] =
                make_float2(acc[mt][nt][0] + bv0, acc[mt][nt][1] + bv1);
            *(float2*)&C[(size_t)(r + 8) * N + cgl] =
                make_float2(acc[mt][nt][2] + bv0, acc[mt][nt][3] + bv1);
        }
    }
#undef GEMM_STAGE
#undef GEMM_COMPUTE
}

// ---------------- fused QKV GEMM: C[TB][1536] = A @ [wq|wk|wv]^T + bias ------
__global__ __launch_bounds__(256, 2)
void gemm_qkv(const float* __restrict__ A,
              const float* __restrict__ wq, const float* __restrict__ wk,
              const float* __restrict__ wv,
              const float* __restrict__ bq, const float* __restrict__ bk,
              const float* __restrict__ bv,
              float* __restrict__ C) {
    __shared__ __align__(16) float As[2][128][20];
    __shared__ __align__(16) float Bs[2][128][20];
    constexpr int K = H_, N = 3 * H_;

    const int tid = threadIdx.x;
    const int lane = tid & 31;
    const int wid = tid >> 5;
    const int wm = (wid & 3) * 32;
    const int wn = (wid >> 2) * 64;
    const int bm = blockIdx.y * 128;
    const int bn = blockIdx.x * 128;
    const int lr = tid >> 1;
    const int lk = (tid & 1) * 8;

    const int wrow = bn + lr;
    const int sel = wrow >> 9;
    const int wl = wrow & 511;
    const float* Wbase = (sel == 0) ? wq : ((sel == 1) ? wk : wv);
    const float* Ap = A + (size_t)(bm + lr) * K + lk;
    const float* Wp = Wbase + (size_t)wl * K + lk;

    float acc[2][8][4];
#pragma unroll
    for (int mt = 0; mt < 2; mt++)
#pragma unroll
        for (int nt = 0; nt < 8; nt++)
#pragma unroll
            for (int q = 0; q < 4; q++) acc[mt][nt][q] = 0.f;

    const int gq = lane >> 2;
    const int tg = lane & 3;

    float4 pa0, pa1, pb0, pb1;
    pa0 = *(const float4*)(Ap);
    pa1 = *(const float4*)(Ap + 4);
    pb0 = *(const float4*)(Wp);
    pb1 = *(const float4*)(Wp + 4);

#define QKV_STAGE(BUF)                                                        \
    {                                                                         \
        float4 ca0 = make_float4(tf32r(pa0.x), tf32r(pa0.y), tf32r(pa0.z), tf32r(pa0.w)); \
        float4 ca1 = make_float4(tf32r(pa1.x), tf32r(pa1.y), tf32r(pa1.z), tf32r(pa1.w)); \
        float4 cb0 = make_float4(tf32r(pb0.x), tf32r(pb0.y), tf32r(pb0.z), tf32r(pb0.w)); \
        float4 cb1 = make_float4(tf32r(pb1.x), tf32r(pb1.y), tf32r(pb1.z), tf32r(pb1.w)); \
        *(float4*)&As[BUF][lr][lk]     = ca0;                                 \
        *(float4*)&As[BUF][lr][lk + 4] = ca1;                                 \
        *(float4*)&Bs[BUF][lr][lk]     = cb0;                                 \
        *(float4*)&Bs[BUF][lr][lk + 4] = cb1;                                 \
    }

#define QKV_COMPUTE(BUF)                                                      \
    _Pragma("unroll")                                                         \
    for (int ks = 0; ks < 16; ks += 8) {                                      \
        float a[2][4];                                                        \
        float b[8][2];                                                        \
        _Pragma("unroll")                                                     \
        for (int mt = 0; mt < 2; mt++) {                                      \
            int r = wm + mt * 16 + gq;                                        \
            int c = ks + tg;                                                  \
            a[mt][0] = As[BUF][r][c];                                         \
            a[mt][1] = As[BUF][r + 8][c];                                     \
            a[mt][2] = As[BUF][r][c + 4];                                     \
            a[mt][3] = As[BUF][r + 8][c + 4];                                 \
        }                                                                     \
        _Pragma("unroll")                                                     \
        for (int nt = 0; nt < 8; nt++) {                                      \
            int n = wn + nt * 8 + gq;                                         \
            b[nt][0] = Bs[BUF][n][ks + tg];                                   \
            b[nt][1] = Bs[BUF][n][ks + tg + 4];                               \
        }                                                                     \
        _Pragma("unroll")                                                     \
        for (int mt = 0; mt < 2; mt++)                                        \
            _Pragma("unroll")                                                 \
            for (int nt = 0; nt < 8; nt++)                                    \
                mma_tf32(acc[mt][nt], a[mt][0], a[mt][1], a[mt][2], a[mt][3], \
                         b[nt][0], b[nt][1]);                                 \
    }

    QKV_STAGE(0)
    __syncthreads();

    int buf = 0;
    for (int k0 = 16; k0 < K; k0 += 16) {
        pa0 = *(const float4*)(Ap + k0);
        pa1 = *(const float4*)(Ap + k0 + 4);
        pb0 = *(const float4*)(Wp + k0);
        pb1 = *(const float4*)(Wp + k0 + 4);
        if (buf == 0) { QKV_COMPUTE(0) QKV_STAGE(1) }
        else          { QKV_COMPUTE(1) QKV_STAGE(0) }
        __syncthreads();
        buf ^= 1;
    }
    if (buf == 0) { QKV_COMPUTE(0) } else { QKV_COMPUTE(1) }

#pragma unroll
    for (int mt = 0; mt < 2; mt++) {
        int r = bm + wm + mt * 16 + gq;
#pragma unroll
        for (int nt = 0; nt < 8; nt++) {
            int cgl = bn + wn + nt * 8 + 2 * tg;
            int selc = cgl >> 9;
            int lc = cgl & 511;
            const float* bb = (selc == 0) ? bq : ((selc == 1) ? bk : bv);
            float bv0 = bb[lc], bv1 = bb[lc + 1];
            *(float2*)&C[(size_t)r * N + cgl] =
                make_float2(acc[mt][nt][0] + bv0, acc[mt][nt][1] + bv1);
            *(float2*)&C[(size_t)(r + 8) * N + cgl] =
                make_float2(acc[mt][nt][2] + bv0, acc[mt][nt][3] + bv1);
        }
    }
#undef QKV_STAGE
#undef QKV_COMPUTE
}

// ---------------- persistent tensor-core LSTM (cp.async staging) ------------
// 128 resident blocks (32 j-strips x 4 b-groups), 256 threads.
// smem: w_hh [64][516], w_ih [64][132], stage[3][64][68]; ps aliases stage[1].
constexpr int WHH_STR = 516;
constexpr int WIH_STR = 132;
constexpr int HS_STR  = 68;
constexpr int WHH_FLOATS = 64 * WHH_STR;     // 33024
constexpr int WIH_FLOATS = 64 * WIH_STR;     // 8448
constexpr int STG_FLOATS = 64 * HS_STR;      // 4352 per buffer
constexpr int LSTM_SMEM_BYTES = (WHH_FLOATS + WIH_FLOATS + 3 * STG_FLOATS) * 4;

__device__ __forceinline__ void lstm_comp(const float* HS, const float* WS,
                                          int wstr, int coff,
                                          int wm, int wn, int gq, int tg,
                                          float (&acc)[2][2][4]) {
#pragma unroll
    for (int ks = 0; ks < 64; ks += 8) {
        float a[2][4];
        float bf[2][2];
#pragma unroll
        for (int mt = 0; mt < 2; mt++) {
            int r = wm + mt * 16 + gq;
            int cc = ks + tg;
            a[mt][0] = HS[r * HS_STR + cc];
            a[mt][1] = HS[(r + 8) * HS_STR + cc];
            a[mt][2] = HS[r * HS_STR + cc + 4];
            a[mt][3] = HS[(r + 8) * HS_STR + cc + 4];
        }
#pragma unroll
        for (int nt = 0; nt < 2; nt++) {
            int n = wn + nt * 8 + gq;
            bf[nt][0] = WS[n * wstr + coff + ks + tg];
            bf[nt][1] = WS[n * wstr + coff + ks + tg + 4];
        }
#pragma unroll
        for (int mt = 0; mt < 2; mt++)
#pragma unroll
            for (int nt = 0; nt < 2; nt++)
                mma_tf32(acc[mt][nt], a[mt][0], a[mt][1], a[mt][2], a[mt][3],
                         bf[nt][0], bf[nt][1]);
    }
}

__global__ __launch_bounds__(256, 1)
void lstm_persistent(const float* __restrict__ w_ih,    // (4H,E)
                     const float* __restrict__ w_hh,    // (4H,H)
                     const int* __restrict__ lengths) {
    extern __shared__ __align__(16) float dsm[];
    float* ws_hh = dsm;
    float* ws_ih = ws_hh + WHH_FLOATS;
    float* stage = ws_ih + WIH_FLOATS;         // 3 buffers of STG_FLOATS
    float* ps    = stage + 1 * STG_FLOATS;     // alias buffer 1

    const int tid = threadIdx.x;
    const int lane = tid & 31;
    const int wid = tid >> 5;
    const int wm = (wid & 1) * 32;
    const int wn = (wid >> 1) * 16;
    const int j0 = (blockIdx.x & 31) * 16;
    const int b0 = (blockIdx.x >> 5) * 64;
    const int grp = blockIdx.x >> 5;

    const int gq = lane >> 2;
    const int tg = lane & 3;

    // load w_hh slice (rows n: gate = n>>4, jl = n&15), tf32 converted
    for (int idx = tid; idx < 64 * 128; idx += 256) {
        int n = idx >> 7;
        int k4 = (idx & 127) * 4;
        int g = n >> 4, jl = n & 15;
        float4 v = *(const float4*)(w_hh + (size_t)(g * H_ + j0 + jl) * H_ + k4);
        float* dst = ws_hh + n * WHH_STR + k4;
        dst[0] = tf32r(v.x); dst[1] = tf32r(v.y);
        dst[2] = tf32r(v.z); dst[3] = tf32r(v.w);
    }
    // load w_ih slice
    for (int idx = tid; idx < 64 * 32; idx += 256) {
        int n = idx >> 5;
        int k4 = (idx & 31) * 4;
        int g = n >> 4, jl = n & 15;
        float4 v = *(const float4*)(w_ih + (size_t)(g * H_ + j0 + jl) * E_ + k4);
        float* dst = ws_ih + n * WIH_STR + k4;
        dst[0] = tf32r(v.x); dst[1] = tf32r(v.y);
        dst[2] = tf32r(v.z); dst[3] = tf32r(v.w);
    }
    __syncthreads();

    // staging indices: row 0..63, cg 0..3 (16 cols = 4x16B each)
    const int row = tid >> 2;
    const int cg = tid & 3;
    const float* e_base = g_embs + (size_t)(b0 + row) * E_ + cg * 16;
    const float* h_base = g_hseq + (size_t)(b0 + row) * H_ + cg * 16;

    uint32_t stage_u32 = (uint32_t)__cvta_generic_to_shared(stage);
    uint32_t stg_u32[3];
#pragma unroll
    for (int bff = 0; bff < 3; bff++)
        stg_u32[bff] = stage_u32 + (uint32_t)(bff * STG_FLOATS + row * HS_STR + cg * 16) * 4u;

    // epilogue cell mapping
    int lenp[4];
    float bi[4], bfo[4], bg[4], bo4[4];
    float creg[4];
#pragma unroll
    for (int p = 0; p < 4; p++) {
        int idx = tid + p * 256;
        int jloc = idx & 15;
        int bl = idx >> 4;
        lenp[p] = lengths[b0 + bl];
        int j = j0 + jloc;
        bi[p]  = g_bsum[j];
        bfo[p] = g_bsum[H_ + j];
        bg[p]  = g_bsum[2 * H_ + j];
        bo4[p] = g_bsum[3 * H_ + j];
        creg[p] = 0.f;
    }

    for (int t = 0; t < T_; t++) {
        const float* e_t = e_base + (size_t)t * B_ * E_;
        const float* h_t = h_base + (size_t)t * B_ * H_;

        // issue chunk c into given buffer (4x16B per thread, one commit group)
        auto issue = [&](int c, uint32_t dst) {
            const float* s = (c < 2) ? (e_t + c * 64) : (h_t + (c - 2) * 64);
            cp16(dst, s); cp16(dst + 16, s + 4);
            cp16(dst + 32, s + 8); cp16(dst + 48, s + 12);
            cp_commit();
        };

        float acc[2][2][4];
#pragma unroll
        for (int mt = 0; mt < 2; mt++)
#pragma unroll
            for (int nt = 0; nt < 2; nt++)
#pragma unroll
                for (int q = 0; q < 4; q++) acc[mt][nt][q] = 0.f;

        issue(0, stg_u32[0]);
        issue(1, stg_u32[1]);

#pragma unroll
        for (int c = 0; c < 10; c++) {
            if (c < 9) cp_wait<1>(); else cp_wait<0>();
            __syncthreads();
            if (c + 2 < 10) issue(c + 2, stg_u32[(c + 2) % 3]);
            const float* HS = stage + (c % 3) * STG_FLOATS;
            if (c < 2)
                lstm_comp(HS, ws_ih, WIH_STR, c * 64, wm, wn, gq, tg, acc);
            else
                lstm_comp(HS, ws_hh, WHH_STR, (c - 2) * 64, wm, wn, gq, tg, acc);
        }

        // preacts -> shared (ps aliases stage[1]: chunk 7, consumed 2 iters ago)
        __syncthreads();
#pragma unroll
        for (int mt = 0; mt < 2; mt++) {
            int r = wm + mt * 16 + gq;
#pragma unroll
            for (int nt = 0; nt < 2; nt++) {
                int c = wn + nt * 8 + 2 * tg;
                *(float2*)&ps[r * HS_STR + c] = make_float2(acc[mt][nt][0], acc[mt][nt][1]);
                *(float2*)&ps[(r + 8) * HS_STR + c] = make_float2(acc[mt][nt][2], acc[mt][nt][3]);
            }
        }
        __syncthreads();

        // gate epilogue: write tf32-rounded h (consumers all round anyway)
        float* hout = g_hseq + (size_t)(t + 1) * B_ * H_;
#pragma unroll
        for (int p = 0; p < 4; p++) {
            int idx = tid + p * 256;
            int jloc = idx & 15;
            int bl = idx >> 4;
            int b = b0 + bl;
            int j = j0 + jloc;
            float gi = sigmoidf_(ps[bl * HS_STR + jloc]      + bi[p]);
            float gf = sigmoidf_(ps[bl * HS_STR + 16 + jloc] + bfo[p]);
            float gg = tanhf(    ps[bl * HS_STR + 32 + jloc] + bg[p]);
            float go = sigmoidf_(ps[bl * HS_STR + 48 + jloc] + bo4[p]);
            float cn = gf * creg[p] + gi * gg;
            creg[p] = cn;
            float hn = tf32r(go * tanhf(cn));
            hout[(size_t)b * H_ + j] = hn;
            g_lstm_out[(size_t)(b * T_ + t) * H_ + j] = (t < lenp[p]) ? hn : 0.f;
        }
        __syncthreads();

        // group barrier (32 blocks sharing b0)
        if (t != T_ - 1) {
            if (tid == 0) {
                __threadfence();
                atomicAdd(&g_bar4[grp * 16], 1u);
                unsigned target = 32u * (unsigned)(t + 1);
                volatile unsigned* vb = &g_bar4[grp * 16];
                while (*vb < target) __nanosleep(32);
            }
            __syncthreads();
        }
    }
}

// ---------------- attention: one block per (b, head), QKV packed ------------
__global__ __launch_bounds__(256)
void attention_kernel(const float* __restrict__ QKV,
                      const int* __restrict__ lengths,
                      float* __restrict__ Wout) {
    __shared__ float qs[64 * 64];
    __shared__ float ks[64 * 64];
    __shared__ float ss[64 * 64];
    const int b = blockIdx.x, nh = blockIdx.y;
    const int tid = threadIdx.x;
    const int len = lengths[b];
    const size_t qkvbase = ((size_t)b * 64) * 1536 + nh * 64;
    const size_t obase = ((size_t)b * 64) * 512 + nh * 64;

#pragma unroll
    for (int l = 0; l < 4; l++) {
        int fidx = tid + (l << 8);
        int r = fidx & 63, c4 = fidx >> 6;
        float4 qv = *(const float4*)(QKV + qkvbase + (size_t)r * 1536 + c4 * 4);
        float4 kv = *(const float4*)(QKV + qkvbase + 512 + (size_t)r * 1536 + c4 * 4);
        qs[(c4 * 4 + 0) * 64 + r] = qv.x; qs[(c4 * 4 + 1) * 64 + r] = qv.y;
        qs[(c4 * 4 + 2) * 64 + r] = qv.z; qs[(c4 * 4 + 3) * 64 + r] = qv.w;
        ks[(c4 * 4 + 0) * 64 + r] = kv.x; ks[(c4 * 4 + 1) * 64 + r] = kv.y;
        ks[(c4 * 4 + 2) * 64 + r] = kv.z; ks[(c4 * 4 + 3) * 64 + r] = kv.w;
    }
    __syncthreads();

    const int tx = tid & 15, ty = tid >> 4;
    const int r0 = ty * 4, c0 = tx * 4;
    float acc[4][4];
#pragma unroll
    for (int i = 0; i < 4; i++)
#pragma unroll
        for (int j = 0; j < 4; j++) acc[i][j] = 0.f;

#pragma unroll 8
    for (int k = 0; k < 64; k++) {
        float4 aq = *(const float4*)&qs[k * 64 + r0];
        float4 bk = *(const float4*)&ks[k * 64 + c0];
        float a[4] = {aq.x, aq.y, aq.z, aq.w};
        float bb[4] = {bk.x, bk.y, bk.z, bk.w};
#pragma unroll
        for (int i = 0; i < 4; i++)
#pragma unroll
            for (int j = 0; j < 4; j++) acc[i][j] += a[i] * bb[j];
    }
#pragma unroll
    for (int i = 0; i < 4; i++)
#pragma unroll
        for (int j = 0; j < 4; j++) {
            int c = c0 + j;
            ss[(r0 + i) * 64 + c] = (c < len) ? acc[i][j] * 0.125f : -1e30f;
        }
    __syncthreads();

    float* vs = qs;
#pragma unroll
    for (int l = 0; l < 4; l++) {
        int fidx = tid + (l << 8);
        int r = fidx >> 4, c4 = fidx & 15;
        ((float4*)vs)[fidx] =
            *(const float4*)(QKV + qkvbase + 1024 + (size_t)r * 1536 + c4 * 4);
    }
    if (tid < 64) {
        float m = -1e30f;
#pragma unroll 8
        for (int c = 0; c < 64; c++) m = fmaxf(m, ss[tid * 64 + c]);
        float s = 0.f;
#pragma unroll 8
        for (int c = 0; c < 64; c++) {
            float e = expf(ss[tid * 64 + c] - m);
            ss[tid * 64 + c] = e;
            s += e;
        }
        float inv = 1.f / s;
#pragma unroll 8
        for (int c = 0; c < 64; c++) ss[tid * 64 + c] *= inv;
    }
    __syncthreads();

    float o[4][4];
#pragma unroll
    for (int i = 0; i < 4; i++)
#pragma unroll
        for (int j = 0; j < 4; j++) o[i][j] = 0.f;
#pragma unroll 8
    for (int k = 0; k < 64; k++) {
        float a[4];
#pragma unroll
        for (int i = 0; i < 4; i++) a[i] = ss[(r0 + i) * 64 + k];
        float4 vv4 = *(const float4*)&vs[k * 64 + c0];
        float vv[4] = {vv4.x, vv4.y, vv4.z, vv4.w};
#pragma unroll
        for (int i = 0; i < 4; i++)
#pragma unroll
            for (int j = 0; j < 4; j++) o[i][j] += a[i] * vv[j];
    }
#pragma unroll
    for (int i = 0; i < 4; i++) {
        float4 ov = make_float4(o[i][0], o[i][1], o[i][2], o[i][3]);
        *(float4*)(Wout + obase + (size_t)(r0 + i) * 512 + c0) = ov;
    }
}

// ---------------- fused meanpool + hidden_to_embedding ----------------------
__global__ __launch_bounds__(128)
void pool_h2e_kernel(const float* __restrict__ w_h2e,
                     const float* __restrict__ b_h2e) {
    __shared__ float sp[H_];
    const int b = blockIdx.x;
    const int tid = threadIdx.x;
    float s0 = 0.f, s1 = 0.f, s2 = 0.f, s3 = 0.f;
    const float* src = g_mho + (size_t)b * 64 * H_ + tid * 4;
#pragma unroll 8
    for (int t = 0; t < 64; t++) {
        float4 v = *(const float4*)(src + (size_t)t * H_);
        s0 += v.x; s1 += v.y; s2 += v.z; s3 += v.w;
    }
    sp[tid * 4 + 0] = s0 * (1.f / 64.f);
    sp[tid * 4 + 1] = s1 * (1.f / 64.f);
    sp[tid * 4 + 2] = s2 * (1.f / 64.f);
    sp[tid * 4 + 3] = s3 * (1.f / 64.f);
    __syncthreads();
    float acc = b_h2e[tid];
    const float* wr = w_h2e + (size_t)tid * H_;
#pragma unroll 8
    for (int k = 0; k < H_; k++) acc += sp[k] * wr[k];
    g_ae[b * E_ + tid] = acc;
}

// ---------------- entry point -----------------------------------------------
extern "C" void kernel_launch(void* const* d_in, const int* in_sizes, int n_in,
                              void* d_out, int out_size) {
    const int*   x       = (const int*)d_in[0];
    const int*   lengths = (const int*)d_in[1];
    const float* emb     = (const float*)d_in[2];
    const float* w_ih    = (const float*)d_in[3];
    const float* w_hh    = (const float*)d_in[4];
    const float* b_ih    = (const float*)d_in[5];
    const float* b_hh    = (const float*)d_in[6];
    const float* wq      = (const float*)d_in[7];
    const float* bq      = (const float*)d_in[8];
    const float* wk      = (const float*)d_in[9];
    const float* bk      = (const float*)d_in[10];
    const float* wv      = (const float*)d_in[11];
    const float* bv      = (const float*)d_in[12];
    const float* wo      = (const float*)d_in[13];
    const float* bo      = (const float*)d_in[14];
    const float* w_h2e   = (const float*)d_in[15];
    const float* b_h2e   = (const float*)d_in[16];
    float* out = (float*)d_out;

    float *p_lo, *p_qkv, *p_w, *p_mho, *p_ae;
    cudaGetSymbolAddress((void**)&p_lo,   g_lstm_out);
    cudaGetSymbolAddress((void**)&p_qkv,  g_QKV);
    cudaGetSymbolAddress((void**)&p_w,    g_wout);
    cudaGetSymbolAddress((void**)&p_mho,  g_mho);
    cudaGetSymbolAddress((void**)&p_ae,   g_ae);

    static bool attr_set = false;
    if (!attr_set) {
        cudaFuncSetAttribute(lstm_persistent,
                             cudaFuncAttributeMaxDynamicSharedMemorySize,
                             LSTM_SMEM_BYTES);
        attr_set = true;
    }

    zero_init_kernel<<<(B_ * H_ + 255) / 256, 256>>>();
    bias_sum_kernel<<<(G4_ + 255) / 256, 256>>>(b_ih, b_hh);
    gather_square_kernel<<<(TB_ * E_ / 4 + 255) / 256, 256>>>(x, emb);

    // LSTM recurrence with folded input GEMM + cp.async staging
    lstm_persistent<<<128, 256, LSTM_SMEM_BYTES>>>(w_ih, w_hh, lengths);

    // fused QKV projection -> [TB][1536]
    gemm_qkv<<<dim3(12, TB_ / 128), 256>>>(p_lo, wq, wk, wv, bq, bk, bv, p_qkv);

    attention_kernel<<<dim3(B_, NH_), 256>>>(p_qkv, lengths, p_w);

    // output projection
    gemm_tf32<false><<<dim3(H_ / 128, TB_ / 128), 256>>>(p_w, wo, bo, p_mho, TB_, H_, H_);

    // fused mean-pool + hidden_to_embedding
    pool_h2e_kernel<<<B_, 128>>>(w_h2e, b_h2e);

    // final scores = ae @ emb^T
    gemm_tf32<true><<<dim3((NITEMS + 127) / 128, B_ / 128), 256>>>(p_ae, emb, nullptr, out, B_, NITEMS, E_);
}